// round 3
// baseline (speedup 1.0000x reference)
#include <cuda_runtime.h>
#include <cuda_bf16.h>
#include <mma.h>
#include <math.h>

using namespace nvcuda;

// ----------------------------------------------------------------------------
// Dimensions
//   B=8, N=2048, D=1028 (pad->1056), H=4*D=4112 (pad->4128), M = B*N = 16384
// All padded K dims divisible by 32; padded regions are exact zeros.
// ----------------------------------------------------------------------------
#define MROWS 16384
#define NPOS  2048
#define NBATCH 8
#define DREAL 1028
#define DP    1056
#define HREAL 4112
#define HP    4128

// ---- scratch (device globals; no runtime allocation allowed) ----
__device__ __nv_bfloat16 g_xb  [(size_t)MROWS * DP];
__device__ __nv_bfloat16 g_q   [(size_t)MROWS * DP];
__device__ __nv_bfloat16 g_k   [(size_t)MROWS * DP];
__device__ __nv_bfloat16 g_v   [(size_t)MROWS * DP];
__device__ __nv_bfloat16 g_attn[(size_t)MROWS * DP];
__device__ __nv_bfloat16 g_h   [(size_t)MROWS * HP];
__device__ float         g_S   [(size_t)NBATCH * NPOS * NPOS];
__device__ __nv_bfloat16 g_P   [(size_t)NBATCH * NPOS * NPOS];
__device__ __nv_bfloat16 g_Wq  [(size_t)DP * DP];
__device__ __nv_bfloat16 g_Wk  [(size_t)DP * DP];
__device__ __nv_bfloat16 g_Wv  [(size_t)DP * DP];
__device__ __nv_bfloat16 g_We  [(size_t)HP * DP];
__device__ __nv_bfloat16 g_Wo  [(size_t)DREAL * HP];

// ----------------------------------------------------------------------------
// fp32 -> bf16 with zero padding:  src [R,C] row-major -> dst [Rp,Cp]
// ----------------------------------------------------------------------------
__global__ void pad_cast_kernel(const float* __restrict__ src,
                                __nv_bfloat16* __restrict__ dst,
                                int R, int C, int Rp, int Cp) {
    size_t idx = (size_t)blockIdx.x * 256 + threadIdx.x;
    size_t total = (size_t)Rp * Cp;
    if (idx >= total) return;
    int r = (int)(idx / Cp);
    int c = (int)(idx % Cp);
    float v = (r < R && c < C) ? src[(size_t)r * C + c] : 0.0f;
    dst[idx] = __float2bfloat16(v);
}

// ----------------------------------------------------------------------------
// Tiled WMMA GEMM, bf16 inputs, fp32 accumulate.
//   BNK = true : C[M,N] = A[M,K] * B[N,K]^T   (B stored row-major [N,K])
//   BNK = false: C[M,N] = A[M,K] * B[K,N]     (B stored row-major [K,N])
// Epilogues (EPI):
//   0: fp32 store (scores)
//   1: bf16((acc + bias) * alpha)        (q/k/v projections)
//   2: bf16(gelu_exact(acc + bias))      (MLP up)
//   3: fp32(acc + bias + x_residual)     (final output)
//   4: bf16(acc)                         (attn * V)
// Block tile 128x128, BK=32, 256 threads (8 warps, 4x2 of 32x64 warp tiles).
// ----------------------------------------------------------------------------
#define BM 128
#define BN 128
#define BK 32
#define BKP 40
#define BNP 136

template <bool BNK, int EPI>
__global__ __launch_bounds__(256)
void gemm_kernel(const __nv_bfloat16* __restrict__ A,
                 const __nv_bfloat16* __restrict__ B,
                 void* __restrict__ Cv,
                 int M, int Nstore, int Nreal, int K,
                 int lda, int ldb, int ldc,
                 const float* __restrict__ bias, int nbias,
                 float alpha,
                 const float* __restrict__ xres,
                 size_t strideA, size_t strideB, size_t strideC) {
    __shared__ __nv_bfloat16 As[BM * BKP];
    __shared__ __nv_bfloat16 Bs[BNK ? (BN * BKP) : (BK * BNP)];
    __shared__ float stage[8 * 256];

    const int tid  = threadIdx.x;
    const int wid  = tid >> 5;
    const int lane = tid & 31;
    const int z    = blockIdx.z;

    A += (size_t)z * strideA;
    B += (size_t)z * strideB;

    const int m0 = blockIdx.y * BM;
    const int n0 = blockIdx.x * BN;
    const int wm = (wid & 3) * 32;   // warp row offset in tile
    const int wn = (wid >> 2) * 64;  // warp col offset in tile

    wmma::fragment<wmma::accumulator, 16, 16, 16, float> acc[2][4];
#pragma unroll
    for (int i = 0; i < 2; i++)
#pragma unroll
        for (int j = 0; j < 4; j++) wmma::fill_fragment(acc[i][j], 0.0f);

    for (int k0 = 0; k0 < K; k0 += BK) {
        // ---- load A tile (M always multiple of 128; K multiple of 32) ----
#pragma unroll
        for (int v = tid; v < BM * BK / 8; v += 256) {
            int r = v >> 2, c = (v & 3) << 3;
            *(float4*)(As + r * BKP + c) =
                *(const float4*)(A + (size_t)(m0 + r) * lda + k0 + c);
        }
        // ---- load B tile ----
        if (BNK) {
#pragma unroll
            for (int v = tid; v < BN * BK / 8; v += 256) {
                int r = v >> 2, c = (v & 3) << 3;
                int gn = n0 + r;
                float4 val = make_float4(0.f, 0.f, 0.f, 0.f);
                if (gn < Nreal)
                    val = *(const float4*)(B + (size_t)gn * ldb + k0 + c);
                *(float4*)(Bs + r * BKP + c) = val;
            }
        } else {
#pragma unroll
            for (int v = tid; v < BK * BN / 8; v += 256) {
                int r = v >> 4, c = (v & 15) << 3;
                int gn = n0 + c;
                float4 val = make_float4(0.f, 0.f, 0.f, 0.f);
                if (gn < Nreal)
                    val = *(const float4*)(B + (size_t)(k0 + r) * ldb + gn);
                *(float4*)(Bs + r * BNP + c) = val;
            }
        }
        __syncthreads();

        // ---- MMA ----
#pragma unroll
        for (int kk = 0; kk < BK; kk += 16) {
            wmma::fragment<wmma::matrix_a, 16, 16, 16, __nv_bfloat16, wmma::row_major> af[2];
#pragma unroll
            for (int i = 0; i < 2; i++)
                wmma::load_matrix_sync(af[i], As + (size_t)(wm + i * 16) * BKP + kk, BKP);
            if (BNK) {
                wmma::fragment<wmma::matrix_b, 16, 16, 16, __nv_bfloat16, wmma::col_major> bf[4];
#pragma unroll
                for (int j = 0; j < 4; j++)
                    wmma::load_matrix_sync(bf[j], Bs + (size_t)(wn + j * 16) * BKP + kk, BKP);
#pragma unroll
                for (int i = 0; i < 2; i++)
#pragma unroll
                    for (int j = 0; j < 4; j++)
                        wmma::mma_sync(acc[i][j], af[i], bf[j], acc[i][j]);
            } else {
                wmma::fragment<wmma::matrix_b, 16, 16, 16, __nv_bfloat16, wmma::row_major> bf[4];
#pragma unroll
                for (int j = 0; j < 4; j++)
                    wmma::load_matrix_sync(bf[j], Bs + (size_t)kk * BNP + wn + j * 16, BNP);
#pragma unroll
                for (int i = 0; i < 2; i++)
#pragma unroll
                    for (int j = 0; j < 4; j++)
                        wmma::mma_sync(acc[i][j], af[i], bf[j], acc[i][j]);
            }
        }
        __syncthreads();
    }

    // ---- epilogue via per-warp shared staging ----
    float* st = stage + wid * 256;
    __nv_bfloat16* Cb = (__nv_bfloat16*)Cv + (size_t)z * strideC;
    float*         Cf = (float*)Cv         + (size_t)z * strideC;

#pragma unroll
    for (int i = 0; i < 2; i++) {
#pragma unroll
        for (int j = 0; j < 4; j++) {
            wmma::store_matrix_sync(st, acc[i][j], 16, wmma::mem_row_major);
            __syncwarp();
#pragma unroll
            for (int e = lane; e < 256; e += 32) {
                int r = e >> 4, c = e & 15;
                int gm = m0 + wm + i * 16 + r;
                int gn = n0 + wn + j * 16 + c;
                if (gn < Nstore) {
                    float val = st[e];
                    if (EPI == 0) {
                        Cf[(size_t)gm * ldc + gn] = val;
                    } else if (EPI == 1) {
                        float b = (gn < nbias) ? bias[gn] : 0.0f;
                        Cb[(size_t)gm * ldc + gn] = __float2bfloat16((val + b) * alpha);
                    } else if (EPI == 2) {
                        float b = (gn < nbias) ? bias[gn] : 0.0f;
                        float t = val + b;
                        float g = 0.5f * t * (1.0f + erff(t * 0.70710678118654752f));
                        Cb[(size_t)gm * ldc + gn] = __float2bfloat16(g);
                    } else if (EPI == 3) {
                        float b = (gn < nbias) ? bias[gn] : 0.0f;
                        Cf[(size_t)gm * ldc + gn] =
                            val + b + xres[(size_t)gm * DREAL + gn];
                    } else {  // 4
                        Cb[(size_t)gm * ldc + gn] = __float2bfloat16(val);
                    }
                }
            }
            __syncwarp();
        }
    }
}

// ----------------------------------------------------------------------------
// Row softmax: S fp32 [rows, 2048] -> P bf16, exact (max-subtracted)
// ----------------------------------------------------------------------------
__global__ __launch_bounds__(256)
void softmax_kernel(const float* __restrict__ S, __nv_bfloat16* __restrict__ P) {
    const size_t row = blockIdx.x;
    const float* s = S + row * (size_t)NPOS;
    __nv_bfloat16* p = P + row * (size_t)NPOS;
    const int tid = threadIdx.x;
    const int wid = tid >> 5, lane = tid & 31;

    float v[8];
    float mx = -1e30f;
#pragma unroll
    for (int i = 0; i < 8; i++) {
        v[i] = s[tid + i * 256];
        mx = fmaxf(mx, v[i]);
    }
    __shared__ float redmax[8];
    __shared__ float redsum[8];
#pragma unroll
    for (int o = 16; o > 0; o >>= 1)
        mx = fmaxf(mx, __shfl_xor_sync(0xffffffffu, mx, o));
    if (lane == 0) redmax[wid] = mx;
    __syncthreads();
    float bm = redmax[0];
#pragma unroll
    for (int i = 1; i < 8; i++) bm = fmaxf(bm, redmax[i]);

    float sum = 0.0f;
#pragma unroll
    for (int i = 0; i < 8; i++) {
        v[i] = __expf(v[i] - bm);
        sum += v[i];
    }
#pragma unroll
    for (int o = 16; o > 0; o >>= 1)
        sum += __shfl_xor_sync(0xffffffffu, sum, o);
    if (lane == 0) redsum[wid] = sum;
    __syncthreads();
    float tot = 0.0f;
#pragma unroll
    for (int i = 0; i < 8; i++) tot += redsum[i];
    float inv = 1.0f / tot;
#pragma unroll
    for (int i = 0; i < 8; i++)
        p[tid + i * 256] = __float2bfloat16(v[i] * inv);
}

// ----------------------------------------------------------------------------
// launch
// ----------------------------------------------------------------------------
static inline void pad_cast(const float* src, void* dst, int R, int C, int Rp, int Cp) {
    size_t total = (size_t)Rp * Cp;
    int blocks = (int)((total + 255) / 256);
    pad_cast_kernel<<<blocks, 256>>>(src, (__nv_bfloat16*)dst, R, C, Rp, Cp);
}

extern "C" void kernel_launch(void* const* d_in, const int* in_sizes, int n_in,
                              void* d_out, int out_size) {
    const float* x  = (const float*)d_in[0];
    const float* Wq = (const float*)d_in[1];
    const float* bq = (const float*)d_in[2];
    const float* Wk = (const float*)d_in[3];
    const float* bk = (const float*)d_in[4];
    const float* Wv = (const float*)d_in[5];
    const float* bv = (const float*)d_in[6];
    const float* We = (const float*)d_in[7];
    const float* be = (const float*)d_in[8];
    const float* Wo = (const float*)d_in[9];
    const float* bo = (const float*)d_in[10];

    void *p_xb, *p_q, *p_k, *p_v, *p_attn, *p_h, *p_S, *p_P;
    void *p_Wq, *p_Wk, *p_Wv, *p_We, *p_Wo;
    cudaGetSymbolAddress(&p_xb, g_xb);
    cudaGetSymbolAddress(&p_q, g_q);
    cudaGetSymbolAddress(&p_k, g_k);
    cudaGetSymbolAddress(&p_v, g_v);
    cudaGetSymbolAddress(&p_attn, g_attn);
    cudaGetSymbolAddress(&p_h, g_h);
    cudaGetSymbolAddress(&p_S, g_S);
    cudaGetSymbolAddress(&p_P, g_P);
    cudaGetSymbolAddress(&p_Wq, g_Wq);
    cudaGetSymbolAddress(&p_Wk, g_Wk);
    cudaGetSymbolAddress(&p_Wv, g_Wv);
    cudaGetSymbolAddress(&p_We, g_We);
    cudaGetSymbolAddress(&p_Wo, g_Wo);

    // 1) casts + padding
    pad_cast(x,  p_xb, MROWS, DREAL, MROWS, DP);
    pad_cast(Wq, p_Wq, DREAL, DREAL, DP, DP);
    pad_cast(Wk, p_Wk, DREAL, DREAL, DP, DP);
    pad_cast(Wv, p_Wv, DREAL, DREAL, DP, DP);
    pad_cast(We, p_We, HREAL, DREAL, HP, DP);
    pad_cast(Wo, p_Wo, DREAL, HREAL, DREAL, HP);

    dim3 blk(256);
    const float qscale = 1.0f / sqrtf((float)DREAL);

    // 2) q/k/v projections: [16384,1056] = xb @ W^T + b
    {
        dim3 grid(DP / BN + (DP % BN ? 1 : 0), MROWS / BM, 1);  // (9,128)
        gemm_kernel<true, 1><<<grid, blk>>>(
            (const __nv_bfloat16*)p_xb, (const __nv_bfloat16*)p_Wq, p_q,
            MROWS, DP, DP, DP, DP, DP, DP, bq, DREAL, qscale, nullptr, 0, 0, 0);
        gemm_kernel<true, 1><<<grid, blk>>>(
            (const __nv_bfloat16*)p_xb, (const __nv_bfloat16*)p_Wk, p_k,
            MROWS, DP, DP, DP, DP, DP, DP, bk, DREAL, 1.0f, nullptr, 0, 0, 0);
        gemm_kernel<true, 1><<<grid, blk>>>(
            (const __nv_bfloat16*)p_xb, (const __nv_bfloat16*)p_Wv, p_v,
            MROWS, DP, DP, DP, DP, DP, DP, bv, DREAL, 1.0f, nullptr, 0, 0, 0);
    }

    // 3) scores: per batch, S = q @ k^T (scale folded into q)
    {
        dim3 grid(NPOS / BN, NPOS / BM, NBATCH);  // (16,16,8)
        gemm_kernel<true, 0><<<grid, blk>>>(
            (const __nv_bfloat16*)p_q, (const __nv_bfloat16*)p_k, p_S,
            NPOS, NPOS, NPOS, DP, DP, DP, NPOS, nullptr, 0, 1.0f, nullptr,
            (size_t)NPOS * DP, (size_t)NPOS * DP, (size_t)NPOS * NPOS);
    }

    // 4) softmax rows
    softmax_kernel<<<NBATCH * NPOS, 256>>>((const float*)p_S, (__nv_bfloat16*)p_P);

    // 5) attn = P @ V  (NN)
    {
        dim3 grid(DP / BN + 1, NPOS / BM, NBATCH);  // (9,16,8)
        gemm_kernel<false, 4><<<grid, blk>>>(
            (const __nv_bfloat16*)p_P, (const __nv_bfloat16*)p_v, p_attn,
            NPOS, DP, DP, NPOS, NPOS, DP, DP, nullptr, 0, 1.0f, nullptr,
            (size_t)NPOS * NPOS, (size_t)NPOS * DP, (size_t)NPOS * DP);
    }

    // 6) h = gelu(attn @ We^T + be)
    {
        dim3 grid(HP / BN + 1, MROWS / BM, 1);  // (33,128)
        gemm_kernel<true, 2><<<grid, blk>>>(
            (const __nv_bfloat16*)p_attn, (const __nv_bfloat16*)p_We, p_h,
            MROWS, HP, HP, DP, DP, DP, HP, be, HREAL, 1.0f, nullptr, 0, 0, 0);
    }

    // 7) out = h @ Wo^T + bo + x   (fp32)
    {
        dim3 grid(DREAL / BN + 1, MROWS / BM, 1);  // (9,128)
        gemm_kernel<true, 3><<<grid, blk>>>(
            (const __nv_bfloat16*)p_h, (const __nv_bfloat16*)p_Wo, d_out,
            MROWS, DREAL, DREAL, HP, HP, HP, DREAL, bo, DREAL, 1.0f, x, 0, 0, 0);
    }
}

// round 5
// speedup vs baseline: 1.2247x; 1.2247x over previous
#include <cuda_runtime.h>
#include <cuda_bf16.h>
#include <mma.h>
#include <cstdint>
#include <math.h>

// ============================================================================
// Dimensions:  B=8, N=2048, D=1028 -> pad 1152 (9*128), H=4112 -> pad 4224
// (33*128). M = B*N = 16384. All tiles exact; padded regions are exact zeros.
// ============================================================================
#define MROWS  16384
#define NPOS   2048
#define NBATCH 8
#define DREAL  1028
#define DP     1152
#define HREAL  4112
#define HP     4224

// tcgen05 is only legal PTX for the arch-specific (sm_103a/sm_100a) targets.
// The harness fatbin also contains a plain compute_103 pass; give that pass a
// WMMA implementation of the same kernel so both PTX passes compile, and the
// driver picks the sm_103a cubin (tcgen05) at load time when it exists.
#if defined(__CUDA_ARCH_FEAT_SM103_ALL) || defined(__CUDA_ARCH_FEAT_SM100_ALL) || defined(__CUDA_ARCH_SPECIFIC__)
#define USE_TCGEN05 1
#else
#define USE_TCGEN05 0
#endif

// ---- scratch (device globals; no runtime allocation allowed) ----
__device__ __nv_bfloat16 g_xb  [(size_t)MROWS * DP];
__device__ __nv_bfloat16 g_q   [(size_t)MROWS * DP];
__device__ __nv_bfloat16 g_k   [(size_t)MROWS * DP];
__device__ __nv_bfloat16 g_v   [(size_t)MROWS * DP];
__device__ __nv_bfloat16 g_vt  [(size_t)NBATCH * DP * NPOS];
__device__ __nv_bfloat16 g_attn[(size_t)MROWS * DP];
__device__ __nv_bfloat16 g_h   [(size_t)MROWS * HP];
__device__ float         g_S   [(size_t)NBATCH * NPOS * NPOS];
__device__ __nv_bfloat16 g_P   [(size_t)NBATCH * NPOS * NPOS];
__device__ __nv_bfloat16 g_Wq  [(size_t)DP * DP];
__device__ __nv_bfloat16 g_Wk  [(size_t)DP * DP];
__device__ __nv_bfloat16 g_Wv  [(size_t)DP * DP];
__device__ __nv_bfloat16 g_We  [(size_t)HP * DP];
__device__ __nv_bfloat16 g_Wo  [(size_t)DP * HP];

// ============================================================================
// PTX helpers (only referenced from the guarded tcgen05 body)
// ============================================================================
__device__ __forceinline__ uint32_t smem_u32(const void* p) {
    uint32_t a;
    asm("{ .reg .u64 t; cvta.to.shared.u64 t, %1; cvt.u32.u64 %0, t; }"
        : "=r"(a) : "l"(p));
    return a;
}

#if USE_TCGEN05
__device__ __forceinline__ uint32_t elect_one() {
    uint32_t p;
    asm volatile("{\n\t.reg .pred p;\n\telect.sync _|p, 0xFFFFFFFF;\n\t"
                 "selp.b32 %0, 1, 0, p;\n\t}" : "=r"(p));
    return p;
}
#define MBAR_INIT(addr, cnt) \
    asm volatile("mbarrier.init.shared.b64 [%0], %1;" :: "r"(addr), "r"(cnt) : "memory")
#define MBAR_WAIT(addr, par) do {                                              \
    uint32_t _m = (addr), _p = (par), _d;                                      \
    asm volatile("{\n\t.reg .pred p;\n\t"                                      \
        "mbarrier.try_wait.parity.acquire.cta.shared::cta.b64 p, [%1], %2;\n\t"\
        "selp.b32 %0, 1, 0, p;\n\t}" : "=r"(_d) : "r"(_m), "r"(_p) : "memory");\
    if (!_d) {                                                                 \
        asm volatile("{\n\t.reg .pred P1;\n\t"                                 \
        "W_%=:\n\t"                                                            \
        "mbarrier.try_wait.parity.acquire.cta.shared::cta.b64 P1, [%0], %1, 0x989680;\n\t" \
        "@P1 bra.uni D_%=;\n\t"                                                \
        "bra.uni W_%=;\n\t"                                                    \
        "D_%=:\n\t}" :: "r"(_m), "r"(_p) : "memory");                          \
    }                                                                          \
} while (0)
#define TC_ALLOC(smem_addr, n) \
    asm volatile("tcgen05.alloc.cta_group::1.sync.aligned.shared::cta.b32 [%0], %1;" \
                 :: "r"(smem_addr), "r"((uint32_t)(n)) : "memory")
#define TC_RELINQ() \
    asm volatile("tcgen05.relinquish_alloc_permit.cta_group::1.sync.aligned;")
#define TC_DEALLOC(tmem, n) \
    asm volatile("tcgen05.dealloc.cta_group::1.sync.aligned.b32 %0, %1;" \
                 :: "r"(tmem), "r"((uint32_t)(n)))
#define TC_COMMIT(mbar) \
    asm volatile("tcgen05.commit.cta_group::1.mbarrier::arrive::one.shared::cluster.b64 [%0];" \
                 :: "r"(mbar) : "memory")
#define TC_FENCE_AFTER()  asm volatile("tcgen05.fence::after_thread_sync;" ::: "memory")
#define TC_FENCE_BEFORE() asm volatile("tcgen05.fence::before_thread_sync;" ::: "memory")
#define FENCE_ASYNC_SHARED() asm volatile("fence.proxy.async.shared::cta;" ::: "memory")
#define TC_WAIT_LD() asm volatile("tcgen05.wait::ld.sync.aligned;" ::: "memory")

#define TC_LD_X32(r, addr)                                                     \
    asm volatile("tcgen05.ld.sync.aligned.32x32b.x32.b32 "                     \
        "{%0, %1, %2, %3, %4, %5, %6, %7, %8, %9, %10, %11, %12, %13, %14, %15,"\
        " %16, %17, %18, %19, %20, %21, %22, %23, %24, %25, %26, %27, %28, %29, %30, %31}, [%32];" \
        : "=r"((r)[0]), "=r"((r)[1]), "=r"((r)[2]), "=r"((r)[3]),              \
          "=r"((r)[4]), "=r"((r)[5]), "=r"((r)[6]), "=r"((r)[7]),              \
          "=r"((r)[8]), "=r"((r)[9]), "=r"((r)[10]), "=r"((r)[11]),            \
          "=r"((r)[12]), "=r"((r)[13]), "=r"((r)[14]), "=r"((r)[15]),          \
          "=r"((r)[16]), "=r"((r)[17]), "=r"((r)[18]), "=r"((r)[19]),          \
          "=r"((r)[20]), "=r"((r)[21]), "=r"((r)[22]), "=r"((r)[23]),          \
          "=r"((r)[24]), "=r"((r)[25]), "=r"((r)[26]), "=r"((r)[27]),          \
          "=r"((r)[28]), "=r"((r)[29]), "=r"((r)[30]), "=r"((r)[31])           \
        : "r"(addr))

// bf16 SS MMA, cta_group::1, kind::f16, fp32 accum
__device__ __forceinline__ void mma_ss(uint32_t d, uint64_t ad, uint64_t bd,
                                       uint32_t idesc, uint32_t en) {
    asm volatile(
        "{\n\t.reg .pred p;\n\tsetp.ne.u32 p, %5, 0;\n\t"
        "tcgen05.mma.cta_group::1.kind::f16 [%0], %1, %2, %3, {%4, %4, %4, %4}, p;\n\t}"
        :: "r"(d), "l"(ad), "l"(bd), "r"(idesc), "r"(0u), "r"(en) : "memory");
}

// K-major SW128 descriptor (validated: LBO=1, SBO=64, layout=2, version=1)
__device__ __forceinline__ uint64_t mk_desc(uint32_t addr) {
    return ((uint64_t)2 << 61) | ((uint64_t)1 << 46) | ((uint64_t)64 << 32) |
           ((uint64_t)1 << 16) | (uint64_t)((addr >> 4) & 0x3FFF);
}
// idesc: F32 accum, BF16 A/B, M=128, N=128 (validated 0x8080490 with N field -> 128)
#define TC_IDESC 0x8200490u
#endif  // USE_TCGEN05

// ============================================================================
// GEMM:  C[M,N] = A[M,K] * B[N,K]^T  (both bf16 row-major, fp32 acc)
// CTA tile 256x128, 256 threads.  Two bodies, one symbol:
//   sm_103a pass  -> tcgen05 SS pipeline (BK=64, 2-stage, TMEM accum)
//   compute_103   -> WMMA fallback (BK=32, 8 warps of 64x64)
// EPI: 0 fp32 | 1 bf16((v+b)*alpha) | 2 bf16(gelu(v+b)) | 3 fp32(v+b+x) | 4 bf16(v)
// ============================================================================
#define SMEM_BYTES (98304 + 1024)

template <int EPI>
__global__ __launch_bounds__(256)
void tc_gemm(const __nv_bfloat16* __restrict__ Ag,
             const __nv_bfloat16* __restrict__ Bg,
             void* __restrict__ Cv,
             int K, int lda, int ldb, int ldc, int Nstore,
             const float* __restrict__ bias, int nbias, float alpha,
             const float* __restrict__ xres,
             size_t sA, size_t sB, size_t sC) {
    extern __shared__ char dsm_raw[];
    const int tid = threadIdx.x;
    const int wid = tid >> 5;
    const int z = blockIdx.z;
    Ag += z * sA;
    Bg += z * sB;
    const int m0 = blockIdx.y * 256;
    const int n0 = blockIdx.x * 128;

#if USE_TCGEN05
    // ------------------------------------------------------------------
    // tcgen05 body
    // ------------------------------------------------------------------
    char* smem = (char*)(((uintptr_t)dsm_raw + 1023) & ~(uintptr_t)1023);
    __shared__ __align__(16) unsigned long long mbar_store[2];
    __shared__ uint32_t tmem_store[1];

    // stage s: A at s*49152 (two 16KB halves), B at s*49152+32768
    char* sA0 = smem;
    char* sB0 = smem + 32768;
    char* sA1 = smem + 49152;
    char* sB1 = smem + 81920;

    const uint32_t mb0 = smem_u32(&mbar_store[0]);
    const uint32_t mb1 = smem_u32(&mbar_store[1]);
    const uint32_t tps = smem_u32(&tmem_store[0]);

    if (wid == 0) { TC_ALLOC(tps, 256); TC_RELINQ(); }
    if (tid == 0) { MBAR_INIT(mb0, 1); MBAR_INIT(mb1, 1); }
    __syncthreads();
    uint32_t tmem;
    asm volatile("ld.shared.b32 %0, [%1];" : "=r"(tmem) : "r"(tps));

    const uint64_t dA[2][2] = {
        {mk_desc(smem_u32(sA0)), mk_desc(smem_u32(sA0 + 16384))},
        {mk_desc(smem_u32(sA1)), mk_desc(smem_u32(sA1 + 16384))}};
    const uint64_t dB[2] = {mk_desc(smem_u32(sB0)), mk_desc(smem_u32(sB1))};

    const int nchunks = K >> 6;
    int ph0 = 0, ph1 = 0;

    for (int c = 0; c < nchunks; c++) {
        const int s = c & 1;
        if (c >= 2) {
            if (s == 0) { MBAR_WAIT(mb0, ph0); ph0 ^= 1; }
            else        { MBAR_WAIT(mb1, ph1); ph1 ^= 1; }
        }
        // ---- warps 1..7 load tiles (SW128 swizzle, 128B rows) ----
        if (tid >= 32) {
            char* sa = s ? sA1 : sA0;
            char* sb = s ? sB1 : sB0;
            const char* Abase = (const char*)(Ag + (size_t)m0 * lda + (size_t)c * 64);
            const char* Bbase = (const char*)(Bg + (size_t)n0 * ldb + (size_t)c * 64);
            const size_t ldab = (size_t)lda * 2, ldbb = (size_t)ldb * 2;
            for (int cid = tid - 32; cid < 2048; cid += 224) {
                int r = cid >> 3, cb = (cid & 7) << 4;
                uint32_t off = ((r & 127) << 7) + cb;
                uint32_t sw = off ^ ((off >> 3) & 0x70);
                *(float4*)(sa + ((r >> 7) << 14) + sw) =
                    *(const float4*)(Abase + (size_t)r * ldab + cb);
            }
            for (int cid = tid - 32; cid < 1024; cid += 224) {
                int r = cid >> 3, cb = (cid & 7) << 4;
                uint32_t off = (r << 7) + cb;
                uint32_t sw = off ^ ((off >> 3) & 0x70);
                *(float4*)(sb + sw) =
                    *(const float4*)(Bbase + (size_t)r * ldbb + cb);
            }
        }
        FENCE_ASYNC_SHARED();
        __syncthreads();
        // ---- warp 0 elected lane issues 8 async MMAs + commit ----
        if (wid == 0) {
            if (elect_one()) {
#pragma unroll
                for (int st = 0; st < 4; st++) {
#pragma unroll
                    for (int h = 0; h < 2; h++) {
                        mma_ss(tmem + h * 128, dA[s][h] + st * 2, dB[s] + st * 2,
                               TC_IDESC, (c > 0 || st > 0) ? 1u : 0u);
                    }
                }
                TC_COMMIT(s ? mb1 : mb0);
            }
        }
    }

    if (nchunks >= 1) MBAR_WAIT(mb0, ph0);
    if (nchunks >= 2) MBAR_WAIT(mb1, ph1);
    TC_FENCE_AFTER();

    // ---- epilogue: warp-group wg = M-half (D column offset), subpartition
    //      sp = rows. Each warp: 32 rows x 128 cols. ----
    {
        const int wg = wid >> 2, sp = wid & 3, lane = tid & 31;
        const int gm = m0 + wg * 128 + sp * 32 + lane;
        float* Cf = (float*)Cv + z * sC;
        __nv_bfloat16* Cb = (__nv_bfloat16*)Cv + z * sC;
#pragma unroll
        for (int b = 0; b < 4; b++) {
            const int gn0 = n0 + b * 32;
            if (gn0 >= Nstore) continue;   // uniform across warp
            uint32_t regs[32];
            TC_LD_X32(regs, tmem + wg * 128 + b * 32);
            TC_WAIT_LD();
            float v[32];
#pragma unroll
            for (int j = 0; j < 32; j++) {
                float t = __uint_as_float(regs[j]);
                const int gn = gn0 + j;
                if (EPI == 1) {
                    float bb = (gn < nbias) ? bias[gn] : 0.0f;
                    t = (t + bb) * alpha;
                } else if (EPI == 2) {
                    float bb = (gn < nbias) ? bias[gn] : 0.0f;
                    float u = t + bb;
                    t = 0.5f * u * (1.0f + erff(u * 0.70710678118654752f));
                } else if (EPI == 3) {
                    float bb = (gn < nbias) ? bias[gn] : 0.0f;
                    t = t + bb;   // residual added below
                }
                v[j] = t;
            }
            const bool full = (gn0 + 32 <= Nstore);
            if (EPI == 0 || EPI == 3) {
                if (full) {
                    if (EPI == 3) {
                        const float4* xr = (const float4*)(xres + (size_t)gm * DREAL + gn0);
                        float4* dst = (float4*)(Cf + (size_t)gm * ldc + gn0);
#pragma unroll
                        for (int q4 = 0; q4 < 8; q4++) {
                            float4 xv = xr[q4];
                            dst[q4] = make_float4(v[q4*4+0] + xv.x, v[q4*4+1] + xv.y,
                                                  v[q4*4+2] + xv.z, v[q4*4+3] + xv.w);
                        }
                    } else {
                        float4* dst = (float4*)(Cf + (size_t)gm * ldc + gn0);
#pragma unroll
                        for (int q4 = 0; q4 < 8; q4++)
                            dst[q4] = make_float4(v[q4*4], v[q4*4+1], v[q4*4+2], v[q4*4+3]);
                    }
                } else {
#pragma unroll
                    for (int j = 0; j < 32; j++) {
                        int gn = gn0 + j;
                        if (gn < Nstore) {
                            float t = v[j];
                            if (EPI == 3) t += xres[(size_t)gm * DREAL + gn];
                            Cf[(size_t)gm * ldc + gn] = t;
                        }
                    }
                }
            } else {  // bf16 outputs
                if (full) {
                    uint32_t pk[16];
#pragma unroll
                    for (int p = 0; p < 16; p++) {
                        __nv_bfloat162 h2 = __floats2bfloat162_rn(v[2*p], v[2*p+1]);
                        pk[p] = *(uint32_t*)&h2;
                    }
                    uint4* dst = (uint4*)(Cb + (size_t)gm * ldc + gn0);
#pragma unroll
                    for (int q4 = 0; q4 < 4; q4++)
                        dst[q4] = make_uint4(pk[q4*4], pk[q4*4+1], pk[q4*4+2], pk[q4*4+3]);
                } else {
#pragma unroll
                    for (int j = 0; j < 32; j++) {
                        int gn = gn0 + j;
                        if (gn < Nstore)
                            Cb[(size_t)gm * ldc + gn] = __float2bfloat16(v[j]);
                    }
                }
            }
        }
        TC_FENCE_BEFORE();
    }
    __syncthreads();
    if (wid == 0) TC_DEALLOC(tmem, 256);

#else
    // ------------------------------------------------------------------
    // WMMA fallback body (compute_103 pass) — 8 warps of 64x64, BK=32
    // ------------------------------------------------------------------
    using namespace nvcuda;
    const int lane = tid & 31;
    __nv_bfloat16* As = (__nv_bfloat16*)dsm_raw;                   // 256 x 40
    __nv_bfloat16* Bs = (__nv_bfloat16*)(dsm_raw + 256 * 40 * 2);  // 128 x 40
    float* stage = (float*)(dsm_raw + 256 * 40 * 2 + 128 * 40 * 2);

    const int wm = (wid & 3) * 64;   // warp M offset in tile
    const int wn = (wid >> 2) * 64;  // warp N offset in tile

    wmma::fragment<wmma::accumulator, 16, 16, 16, float> acc[4][4];
#pragma unroll
    for (int i = 0; i < 4; i++)
#pragma unroll
        for (int j = 0; j < 4; j++) wmma::fill_fragment(acc[i][j], 0.0f);

    for (int k0 = 0; k0 < K; k0 += 32) {
#pragma unroll
        for (int vv = tid; vv < 256 * 32 / 8; vv += 256) {
            int r = vv >> 2, c = (vv & 3) << 3;
            *(float4*)(As + r * 40 + c) =
                *(const float4*)(Ag + (size_t)(m0 + r) * lda + k0 + c);
        }
#pragma unroll
        for (int vv = tid; vv < 128 * 32 / 8; vv += 256) {
            int r = vv >> 2, c = (vv & 3) << 3;
            *(float4*)(Bs + r * 40 + c) =
                *(const float4*)(Bg + (size_t)(n0 + r) * ldb + k0 + c);
        }
        __syncthreads();
#pragma unroll
        for (int kk = 0; kk < 32; kk += 16) {
            wmma::fragment<wmma::matrix_a, 16, 16, 16, __nv_bfloat16, wmma::row_major> af[4];
            wmma::fragment<wmma::matrix_b, 16, 16, 16, __nv_bfloat16, wmma::col_major> bf[4];
#pragma unroll
            for (int i = 0; i < 4; i++)
                wmma::load_matrix_sync(af[i], As + (size_t)(wm + i * 16) * 40 + kk, 40);
#pragma unroll
            for (int j = 0; j < 4; j++)
                wmma::load_matrix_sync(bf[j], Bs + (size_t)(wn + j * 16) * 40 + kk, 40);
#pragma unroll
            for (int i = 0; i < 4; i++)
#pragma unroll
                for (int j = 0; j < 4; j++)
                    wmma::mma_sync(acc[i][j], af[i], bf[j], acc[i][j]);
        }
        __syncthreads();
    }

    float* st = stage + wid * 256;
    float* Cf = (float*)Cv + z * sC;
    __nv_bfloat16* Cb = (__nv_bfloat16*)Cv + z * sC;
#pragma unroll
    for (int i = 0; i < 4; i++) {
#pragma unroll
        for (int j = 0; j < 4; j++) {
            wmma::store_matrix_sync(st, acc[i][j], 16, wmma::mem_row_major);
            __syncwarp();
#pragma unroll
            for (int e = lane; e < 256; e += 32) {
                int r = e >> 4, c = e & 15;
                int gm = m0 + wm + i * 16 + r;
                int gn = n0 + wn + j * 16 + c;
                if (gn < Nstore) {
                    float val = st[e];
                    if (EPI == 0) {
                        Cf[(size_t)gm * ldc + gn] = val;
                    } else if (EPI == 1) {
                        float b = (gn < nbias) ? bias[gn] : 0.0f;
                        Cb[(size_t)gm * ldc + gn] = __float2bfloat16((val + b) * alpha);
                    } else if (EPI == 2) {
                        float b = (gn < nbias) ? bias[gn] : 0.0f;
                        float t = val + b;
                        float g = 0.5f * t * (1.0f + erff(t * 0.70710678118654752f));
                        Cb[(size_t)gm * ldc + gn] = __float2bfloat16(g);
                    } else if (EPI == 3) {
                        float b = (gn < nbias) ? bias[gn] : 0.0f;
                        Cf[(size_t)gm * ldc + gn] =
                            val + b + xres[(size_t)gm * DREAL + gn];
                    } else {
                        Cb[(size_t)gm * ldc + gn] = __float2bfloat16(val);
                    }
                }
            }
            __syncwarp();
        }
    }
#endif  // USE_TCGEN05
}

// ============================================================================
// fp32 -> bf16 with zero padding
// ============================================================================
__global__ void pad_cast_kernel(const float* __restrict__ src,
                                __nv_bfloat16* __restrict__ dst,
                                int R, int C, int Rp, int Cp) {
    size_t idx = (size_t)blockIdx.x * 256 + threadIdx.x;
    size_t total = (size_t)Rp * Cp;
    if (idx >= total) return;
    int r = (int)(idx / Cp), c = (int)(idx % Cp);
    float v = (r < R && c < C) ? src[(size_t)r * C + c] : 0.0f;
    dst[idx] = __float2bfloat16(v);
}

// ============================================================================
// per-batch transpose: v[z][n][d] (DP wide) -> vt[z][d][n] (NPOS wide)
// ============================================================================
__global__ __launch_bounds__(256)
void transpose_kernel(const __nv_bfloat16* __restrict__ v,
                      __nv_bfloat16* __restrict__ vt) {
    __shared__ __nv_bfloat16 t[32][33];
    const int z = blockIdx.z;
    const int nb = blockIdx.x * 32, db = blockIdx.y * 32;
    const int tx = threadIdx.x & 31, ty = threadIdx.x >> 5;
    const __nv_bfloat16* vsrc = v + (size_t)z * NPOS * DP;
    __nv_bfloat16* vdst = vt + (size_t)z * DP * NPOS;
#pragma unroll
    for (int i = 0; i < 4; i++)
        t[ty + i * 8][tx] = vsrc[(size_t)(nb + ty + i * 8) * DP + db + tx];
    __syncthreads();
#pragma unroll
    for (int i = 0; i < 4; i++)
        vdst[(size_t)(db + ty + i * 8) * NPOS + nb + tx] = t[tx][ty + i * 8];
}

// ============================================================================
// Row softmax: S fp32 [rows, 2048] -> P bf16
// ============================================================================
__global__ __launch_bounds__(256)
void softmax_kernel(const float* __restrict__ S, __nv_bfloat16* __restrict__ P) {
    const size_t row = blockIdx.x;
    const float* s = S + row * (size_t)NPOS;
    __nv_bfloat16* p = P + row * (size_t)NPOS;
    const int tid = threadIdx.x, wid = tid >> 5, lane = tid & 31;
    float v[8], mx = -1e30f;
#pragma unroll
    for (int i = 0; i < 8; i++) { v[i] = s[tid + i * 256]; mx = fmaxf(mx, v[i]); }
    __shared__ float rm[8], rs[8];
#pragma unroll
    for (int o = 16; o > 0; o >>= 1) mx = fmaxf(mx, __shfl_xor_sync(~0u, mx, o));
    if (lane == 0) rm[wid] = mx;
    __syncthreads();
    float bm = rm[0];
#pragma unroll
    for (int i = 1; i < 8; i++) bm = fmaxf(bm, rm[i]);
    float sum = 0.0f;
#pragma unroll
    for (int i = 0; i < 8; i++) { v[i] = __expf(v[i] - bm); sum += v[i]; }
#pragma unroll
    for (int o = 16; o > 0; o >>= 1) sum += __shfl_xor_sync(~0u, sum, o);
    if (lane == 0) rs[wid] = sum;
    __syncthreads();
    float tot = 0.0f;
#pragma unroll
    for (int i = 0; i < 8; i++) tot += rs[i];
    float inv = 1.0f / tot;
#pragma unroll
    for (int i = 0; i < 8; i++) p[tid + i * 256] = __float2bfloat16(v[i] * inv);
}

// ============================================================================
// launch
// ============================================================================
static inline void pad_cast(const float* src, void* dst, int R, int C, int Rp, int Cp) {
    size_t total = (size_t)Rp * Cp;
    pad_cast_kernel<<<(int)((total + 255) / 256), 256>>>(src, (__nv_bfloat16*)dst, R, C, Rp, Cp);
}

extern "C" void kernel_launch(void* const* d_in, const int* in_sizes, int n_in,
                              void* d_out, int out_size) {
    const float* x  = (const float*)d_in[0];
    const float* Wq = (const float*)d_in[1];
    const float* bq = (const float*)d_in[2];
    const float* Wk = (const float*)d_in[3];
    const float* bk = (const float*)d_in[4];
    const float* Wv = (const float*)d_in[5];
    const float* bv = (const float*)d_in[6];
    const float* We = (const float*)d_in[7];
    const float* be = (const float*)d_in[8];
    const float* Wo = (const float*)d_in[9];
    const float* bo = (const float*)d_in[10];

    void *p_xb, *p_q, *p_k, *p_v, *p_vt, *p_attn, *p_h, *p_S, *p_P;
    void *p_Wq, *p_Wk, *p_Wv, *p_We, *p_Wo;
    cudaGetSymbolAddress(&p_xb, g_xb);
    cudaGetSymbolAddress(&p_q, g_q);
    cudaGetSymbolAddress(&p_k, g_k);
    cudaGetSymbolAddress(&p_v, g_v);
    cudaGetSymbolAddress(&p_vt, g_vt);
    cudaGetSymbolAddress(&p_attn, g_attn);
    cudaGetSymbolAddress(&p_h, g_h);
    cudaGetSymbolAddress(&p_S, g_S);
    cudaGetSymbolAddress(&p_P, g_P);
    cudaGetSymbolAddress(&p_Wq, g_Wq);
    cudaGetSymbolAddress(&p_Wk, g_Wk);
    cudaGetSymbolAddress(&p_Wv, g_Wv);
    cudaGetSymbolAddress(&p_We, g_We);
    cudaGetSymbolAddress(&p_Wo, g_Wo);

    cudaFuncSetAttribute(tc_gemm<0>, cudaFuncAttributeMaxDynamicSharedMemorySize, SMEM_BYTES);
    cudaFuncSetAttribute(tc_gemm<1>, cudaFuncAttributeMaxDynamicSharedMemorySize, SMEM_BYTES);
    cudaFuncSetAttribute(tc_gemm<2>, cudaFuncAttributeMaxDynamicSharedMemorySize, SMEM_BYTES);
    cudaFuncSetAttribute(tc_gemm<3>, cudaFuncAttributeMaxDynamicSharedMemorySize, SMEM_BYTES);
    cudaFuncSetAttribute(tc_gemm<4>, cudaFuncAttributeMaxDynamicSharedMemorySize, SMEM_BYTES);

    // 1) casts + padding (padded regions exact zero)
    pad_cast(x,  p_xb, MROWS, DREAL, MROWS, DP);
    pad_cast(Wq, p_Wq, DREAL, DREAL, DP, DP);
    pad_cast(Wk, p_Wk, DREAL, DREAL, DP, DP);
    pad_cast(Wv, p_Wv, DREAL, DREAL, DP, DP);
    pad_cast(We, p_We, HREAL, DREAL, HP, DP);
    pad_cast(Wo, p_Wo, DREAL, HREAL, DP, HP);

    const float qscale = 1.0f / sqrtf((float)DREAL);
    dim3 blk(256);

    // 2) q/k/v projections: [16384,1152] = xb @ W^T + b
    {
        dim3 grid(DP / 128, MROWS / 256, 1);  // (9,64)
        tc_gemm<1><<<grid, blk, SMEM_BYTES>>>(
            (const __nv_bfloat16*)p_xb, (const __nv_bfloat16*)p_Wq, p_q,
            DP, DP, DP, DP, DP, bq, DREAL, qscale, nullptr, 0, 0, 0);
        tc_gemm<1><<<grid, blk, SMEM_BYTES>>>(
            (const __nv_bfloat16*)p_xb, (const __nv_bfloat16*)p_Wk, p_k,
            DP, DP, DP, DP, DP, bk, DREAL, 1.0f, nullptr, 0, 0, 0);
        tc_gemm<1><<<grid, blk, SMEM_BYTES>>>(
            (const __nv_bfloat16*)p_xb, (const __nv_bfloat16*)p_Wv, p_v,
            DP, DP, DP, DP, DP, bv, DREAL, 1.0f, nullptr, 0, 0, 0);
    }

    // 3) scores: per batch, S = q @ k^T (scale folded into q)
    {
        dim3 grid(NPOS / 128, NPOS / 256, NBATCH);  // (16,8,8)
        tc_gemm<0><<<grid, blk, SMEM_BYTES>>>(
            (const __nv_bfloat16*)p_q, (const __nv_bfloat16*)p_k, p_S,
            DP, DP, DP, NPOS, NPOS, nullptr, 0, 1.0f, nullptr,
            (size_t)NPOS * DP, (size_t)NPOS * DP, (size_t)NPOS * NPOS);
    }

    // 4) softmax rows
    softmax_kernel<<<NBATCH * NPOS, 256>>>((const float*)p_S, (__nv_bfloat16*)p_P);

    // 5) transpose V per batch: v[n,d] -> vt[d,n]
    {
        dim3 grid(NPOS / 32, DP / 32, NBATCH);  // (64,36,8)
        transpose_kernel<<<grid, blk>>>((const __nv_bfloat16*)p_v,
                                        (__nv_bfloat16*)p_vt);
    }

    // 6) attn = P @ V = P @ (Vt)^T
    {
        dim3 grid(DP / 128, NPOS / 256, NBATCH);  // (9,8,8)
        tc_gemm<4><<<grid, blk, SMEM_BYTES>>>(
            (const __nv_bfloat16*)p_P, (const __nv_bfloat16*)p_vt, p_attn,
            NPOS, NPOS, NPOS, DP, DP, nullptr, 0, 1.0f, nullptr,
            (size_t)NPOS * NPOS, (size_t)DP * NPOS, (size_t)NPOS * DP);
    }

    // 7) h = gelu(attn @ We^T + be)
    {
        dim3 grid(HP / 128, MROWS / 256, 1);  // (33,64)
        tc_gemm<2><<<grid, blk, SMEM_BYTES>>>(
            (const __nv_bfloat16*)p_attn, (const __nv_bfloat16*)p_We, p_h,
            DP, DP, DP, HP, HP, be, HREAL, 1.0f, nullptr, 0, 0, 0);
    }

    // 8) out = h @ Wo^T + bo + x  (fp32, width 1028 guarded)
    {
        dim3 grid((DREAL + 127) / 128, MROWS / 256, 1);  // (9,64)
        tc_gemm<3><<<grid, blk, SMEM_BYTES>>>(
            (const __nv_bfloat16*)p_h, (const __nv_bfloat16*)p_Wo, d_out,
            HP, HP, HP, DREAL, DREAL, bo, DREAL, 1.0f, x, 0, 0, 0);
    }
}

// round 7
// speedup vs baseline: 2.5317x; 2.0672x over previous
#include <cuda_runtime.h>
#include <cuda_bf16.h>
#include <mma.h>
#include <cstdint>
#include <math.h>

// ============================================================================
// Dimensions:  B=8, N=2048, D=1028 -> pad 1152 (9*128), H=4112 -> pad 4224
// (33*128). M = B*N = 16384. All tiles exact; padded regions are exact zeros.
// ============================================================================
#define MROWS  16384
#define NPOS   2048
#define NBATCH 8
#define DREAL  1028
#define DP     1152
#define HREAL  4112
#define HP     4224

// tcgen05 is only legal PTX for the arch-specific (sm_103a/sm_100a) targets.
// The harness fatbin also contains a plain compute_103 pass; give that pass a
// WMMA implementation of the same kernel so both PTX passes compile, and the
// driver picks the sm_103a cubin (tcgen05) at load time when it exists.
#if defined(__CUDA_ARCH_FEAT_SM103_ALL) || defined(__CUDA_ARCH_FEAT_SM100_ALL) || defined(__CUDA_ARCH_SPECIFIC__)
#define USE_TCGEN05 1
#else
#define USE_TCGEN05 0
#endif

// ---- scratch (device globals; no runtime allocation allowed) ----
__device__ __nv_bfloat16 g_xb  [(size_t)MROWS * DP];
__device__ __nv_bfloat16 g_q   [(size_t)MROWS * DP];
__device__ __nv_bfloat16 g_k   [(size_t)MROWS * DP];
__device__ __nv_bfloat16 g_v   [(size_t)MROWS * DP];
__device__ __nv_bfloat16 g_vt  [(size_t)NBATCH * DP * NPOS];
__device__ __nv_bfloat16 g_attn[(size_t)MROWS * DP];
__device__ __nv_bfloat16 g_h   [(size_t)MROWS * HP];
__device__ float         g_S   [(size_t)NBATCH * NPOS * NPOS];
__device__ __nv_bfloat16 g_P   [(size_t)NBATCH * NPOS * NPOS];
__device__ __nv_bfloat16 g_Wq  [(size_t)DP * DP];
__device__ __nv_bfloat16 g_Wk  [(size_t)DP * DP];
__device__ __nv_bfloat16 g_Wv  [(size_t)DP * DP];
__device__ __nv_bfloat16 g_We  [(size_t)HP * DP];
__device__ __nv_bfloat16 g_Wo  [(size_t)DP * HP];

// ============================================================================
// PTX helpers
// ============================================================================
__device__ __forceinline__ uint32_t smem_u32(const void* p) {
    uint32_t a;
    asm("{ .reg .u64 t; cvta.to.shared.u64 t, %1; cvt.u32.u64 %0, t; }"
        : "=r"(a) : "l"(p));
    return a;
}
// cp.async (Ampere+: valid in both compile passes)
#define CP_ASYNC16(dst, src) \
    asm volatile("cp.async.cg.shared.global [%0], [%1], 16;" \
                 :: "r"(dst), "l"(src) : "memory")
#define CP_COMMIT() asm volatile("cp.async.commit_group;" ::: "memory")
#define CP_WAIT(n)  asm volatile("cp.async.wait_group %0;" :: "n"(n) : "memory")

#if USE_TCGEN05
__device__ __forceinline__ uint32_t elect_one() {
    uint32_t p;
    asm volatile("{\n\t.reg .pred p;\n\telect.sync _|p, 0xFFFFFFFF;\n\t"
                 "selp.b32 %0, 1, 0, p;\n\t}" : "=r"(p));
    return p;
}
#define MBAR_INIT(addr, cnt) \
    asm volatile("mbarrier.init.shared.b64 [%0], %1;" :: "r"(addr), "r"(cnt) : "memory")
#define MBAR_WAIT(addr, par) do {                                              \
    uint32_t _m = (addr), _p = (par), _d;                                      \
    asm volatile("{\n\t.reg .pred p;\n\t"                                      \
        "mbarrier.try_wait.parity.acquire.cta.shared::cta.b64 p, [%1], %2;\n\t"\
        "selp.b32 %0, 1, 0, p;\n\t}" : "=r"(_d) : "r"(_m), "r"(_p) : "memory");\
    if (!_d) {                                                                 \
        asm volatile("{\n\t.reg .pred P1;\n\t"                                 \
        "W_%=:\n\t"                                                            \
        "mbarrier.try_wait.parity.acquire.cta.shared::cta.b64 P1, [%0], %1, 0x989680;\n\t" \
        "@P1 bra.uni D_%=;\n\t"                                                \
        "bra.uni W_%=;\n\t"                                                    \
        "D_%=:\n\t}" :: "r"(_m), "r"(_p) : "memory");                          \
    }                                                                          \
} while (0)
#define TC_ALLOC(smem_addr, n) \
    asm volatile("tcgen05.alloc.cta_group::1.sync.aligned.shared::cta.b32 [%0], %1;" \
                 :: "r"(smem_addr), "r"((uint32_t)(n)) : "memory")
#define TC_RELINQ() \
    asm volatile("tcgen05.relinquish_alloc_permit.cta_group::1.sync.aligned;")
#define TC_DEALLOC(tmem, n) \
    asm volatile("tcgen05.dealloc.cta_group::1.sync.aligned.b32 %0, %1;" \
                 :: "r"(tmem), "r"((uint32_t)(n)))
#define TC_COMMIT(mbar) \
    asm volatile("tcgen05.commit.cta_group::1.mbarrier::arrive::one.shared::cluster.b64 [%0];" \
                 :: "r"(mbar) : "memory")
#define TC_FENCE_AFTER()  asm volatile("tcgen05.fence::after_thread_sync;" ::: "memory")
#define TC_FENCE_BEFORE() asm volatile("tcgen05.fence::before_thread_sync;" ::: "memory")
#define FENCE_ASYNC_SHARED() asm volatile("fence.proxy.async.shared::cta;" ::: "memory")
#define TC_WAIT_LD() asm volatile("tcgen05.wait::ld.sync.aligned;" ::: "memory")

#define TC_LD_X32(r, addr)                                                     \
    asm volatile("tcgen05.ld.sync.aligned.32x32b.x32.b32 "                     \
        "{%0, %1, %2, %3, %4, %5, %6, %7, %8, %9, %10, %11, %12, %13, %14, %15,"\
        " %16, %17, %18, %19, %20, %21, %22, %23, %24, %25, %26, %27, %28, %29, %30, %31}, [%32];" \
        : "=r"((r)[0]), "=r"((r)[1]), "=r"((r)[2]), "=r"((r)[3]),              \
          "=r"((r)[4]), "=r"((r)[5]), "=r"((r)[6]), "=r"((r)[7]),              \
          "=r"((r)[8]), "=r"((r)[9]), "=r"((r)[10]), "=r"((r)[11]),            \
          "=r"((r)[12]), "=r"((r)[13]), "=r"((r)[14]), "=r"((r)[15]),          \
          "=r"((r)[16]), "=r"((r)[17]), "=r"((r)[18]), "=r"((r)[19]),          \
          "=r"((r)[20]), "=r"((r)[21]), "=r"((r)[22]), "=r"((r)[23]),          \
          "=r"((r)[24]), "=r"((r)[25]), "=r"((r)[26]), "=r"((r)[27]),          \
          "=r"((r)[28]), "=r"((r)[29]), "=r"((r)[30]), "=r"((r)[31])           \
        : "r"(addr))

// bf16 SS MMA, cta_group::1, kind::f16, fp32 accum
__device__ __forceinline__ void mma_ss(uint32_t d, uint64_t ad, uint64_t bd,
                                       uint32_t idesc, uint32_t en) {
    asm volatile(
        "{\n\t.reg .pred p;\n\tsetp.ne.u32 p, %5, 0;\n\t"
        "tcgen05.mma.cta_group::1.kind::f16 [%0], %1, %2, %3, {%4, %4, %4, %4}, p;\n\t}"
        :: "r"(d), "l"(ad), "l"(bd), "r"(idesc), "r"(0u), "r"(en) : "memory");
}

// K-major SW128 descriptor (validated: LBO=1, SBO=64, layout=2, version=1)
__device__ __forceinline__ uint64_t mk_desc(uint32_t addr) {
    return ((uint64_t)2 << 61) | ((uint64_t)1 << 46) | ((uint64_t)64 << 32) |
           ((uint64_t)1 << 16) | (uint64_t)((addr >> 4) & 0x3FFF);
}
// idesc: F32 accum, BF16 A/B, M=128, N=128 (validated 0x8080490 with N -> 128)
#define TC_IDESC 0x8200490u
#endif  // USE_TCGEN05

// ============================================================================
// GEMM:  C[M,N] = A[M,K] * B[N,K]^T  (both bf16 row-major, fp32 acc)
// CTA tile 256x128, 256 threads.  Two bodies, one symbol:
//   sm_103a pass  -> tcgen05 SS pipeline (BK=64, 4-stage cp.async, TMEM accum)
//   compute_103   -> WMMA fallback (BK=32, 2-stage cp.async, 8 warps of 64x64)
// EPI: 0 fp32 | 1 bf16((v+b)*alpha) | 2 bf16(gelu(v+b)) | 3 fp32(v+b+x) | 4 bf16(v)
// ============================================================================
#define SMEM_BYTES (4 * 49152 + 1024)

template <int EPI>
__global__ __launch_bounds__(256)
void tc_gemm(const __nv_bfloat16* __restrict__ Ag,
             const __nv_bfloat16* __restrict__ Bg,
             void* __restrict__ Cv,
             int K, int lda, int ldb, int ldc, int Nstore,
             const float* __restrict__ bias, int nbias, float alpha,
             const float* __restrict__ xres,
             size_t sA, size_t sB, size_t sC) {
    extern __shared__ char dsm_raw[];
    const int tid = threadIdx.x;
    const int wid = tid >> 5;
    const int z = blockIdx.z;
    Ag += z * sA;
    Bg += z * sB;
    const int m0 = blockIdx.y * 256;
    const int n0 = blockIdx.x * 128;

#if USE_TCGEN05
    // ------------------------------------------------------------------
    // tcgen05 body — 4-stage cp.async pipeline
    // ------------------------------------------------------------------
    char* smem = (char*)(((uintptr_t)dsm_raw + 1023) & ~(uintptr_t)1023);
    __shared__ __align__(16) unsigned long long mbar_store[4];
    __shared__ uint32_t tmem_store[1];

    const uint32_t smb = smem_u32(smem);
    uint32_t slotA[4], slotB[4];
    uint64_t dAh[4][2], dBv[4];
#pragma unroll
    for (int s = 0; s < 4; s++) {
        slotA[s] = smb + s * 49152;
        slotB[s] = slotA[s] + 32768;
        dAh[s][0] = mk_desc(slotA[s]);
        dAh[s][1] = mk_desc(slotA[s] + 16384);
        dBv[s] = mk_desc(slotB[s]);
    }
    uint32_t mb[4];
#pragma unroll
    for (int s = 0; s < 4; s++) mb[s] = smem_u32(&mbar_store[s]);
    const uint32_t tps = smem_u32(&tmem_store[0]);

    if (wid == 0) { TC_ALLOC(tps, 256); TC_RELINQ(); }
    if (tid == 0) {
#pragma unroll
        for (int s = 0; s < 4; s++) MBAR_INIT(mb[s], 1);
    }
    __syncthreads();
    uint32_t tmem;
    asm volatile("ld.shared.b32 %0, [%1];" : "=r"(tmem) : "r"(tps));

    const int nc = K >> 6;
    const size_t ldab = (size_t)lda * 2, ldbb = (size_t)ldb * 2;
    const char* Abase = (const char*)(Ag + (size_t)m0 * lda);
    const char* Bbase = (const char*)(Bg + (size_t)n0 * ldb);
    int phase[4] = {0, 0, 0, 0};

    for (int c = 0; c < nc + 3; c++) {
        if (c < nc) {
            const int s = c & 3;
            if (c >= 4) { MBAR_WAIT(mb[s], phase[s]); phase[s] ^= 1; }
            const char* Ab = Abase + (size_t)c * 128;  // 64 bf16 = 128 bytes
            const char* Bb = Bbase + (size_t)c * 128;
            const uint32_t sa = slotA[s], sb = slotB[s];
#pragma unroll
            for (int i = 0; i < 8; i++) {           // A: 256 rows x 128B
                int cid = tid + i * 256;
                int r = cid >> 3, cb = (cid & 7) << 4;
                uint32_t off = ((r & 127) << 7) + cb;
                uint32_t sw = off ^ ((off >> 3) & 0x70);
                CP_ASYNC16(sa + ((r >> 7) << 14) + sw, Ab + (size_t)r * ldab + cb);
            }
#pragma unroll
            for (int i = 0; i < 4; i++) {           // B: 128 rows x 128B
                int cid = tid + i * 256;
                int r = cid >> 3, cb = (cid & 7) << 4;
                uint32_t off = (r << 7) + cb;
                uint32_t sw = off ^ ((off >> 3) & 0x70);
                CP_ASYNC16(sb + sw, Bb + (size_t)r * ldbb + cb);
            }
        }
        CP_COMMIT();   // one group per iteration (possibly empty in tail)
        if (c >= 3) {
            CP_WAIT(3);            // group (c-3) complete for this thread
            FENCE_ASYNC_SHARED();  // writer-side generic->async visibility
            __syncthreads();       // all threads' fills visible
            const int cc = c - 3, s2 = cc & 3;
            if (wid == 0) {
                if (elect_one()) {
#pragma unroll
                    for (int st = 0; st < 4; st++) {
#pragma unroll
                        for (int h = 0; h < 2; h++) {
                            mma_ss(tmem + h * 128, dAh[s2][h] + st * 2,
                                   dBv[s2] + st * 2, TC_IDESC,
                                   (cc > 0 || st > 0) ? 1u : 0u);
                        }
                    }
                    TC_COMMIT(mb[s2]);
                }
            }
        }
    }
#pragma unroll
    for (int s = 0; s < 4; s++) MBAR_WAIT(mb[s], phase[s]);
    TC_FENCE_AFTER();

    // ---- epilogue: warp-group wg = M-half (D column offset), subpartition
    //      sp = rows. Each warp: 32 rows x 128 cols. ----
    {
        const int wg = wid >> 2, sp = wid & 3, lane = tid & 31;
        const int gm = m0 + wg * 128 + sp * 32 + lane;
        float* Cf = (float*)Cv + z * sC;
        __nv_bfloat16* Cb = (__nv_bfloat16*)Cv + z * sC;
#pragma unroll
        for (int b = 0; b < 4; b++) {
            const int gn0 = n0 + b * 32;
            if (gn0 >= Nstore) continue;   // uniform across warp
            uint32_t regs[32];
            TC_LD_X32(regs, tmem + wg * 128 + b * 32);
            TC_WAIT_LD();
            float v[32];
#pragma unroll
            for (int j = 0; j < 32; j++) {
                float t = __uint_as_float(regs[j]);
                const int gn = gn0 + j;
                if (EPI == 1) {
                    float bb = (gn < nbias) ? bias[gn] : 0.0f;
                    t = (t + bb) * alpha;
                } else if (EPI == 2) {
                    float bb = (gn < nbias) ? bias[gn] : 0.0f;
                    float u = t + bb;
                    t = 0.5f * u * (1.0f + erff(u * 0.70710678118654752f));
                } else if (EPI == 3) {
                    float bb = (gn < nbias) ? bias[gn] : 0.0f;
                    t = t + bb;   // residual added below
                }
                v[j] = t;
            }
            const bool full = (gn0 + 32 <= Nstore);
            if (EPI == 0 || EPI == 3) {
                if (full) {
                    if (EPI == 3) {
                        const float4* xr = (const float4*)(xres + (size_t)gm * DREAL + gn0);
                        float4* dst = (float4*)(Cf + (size_t)gm * ldc + gn0);
#pragma unroll
                        for (int q4 = 0; q4 < 8; q4++) {
                            float4 xv = xr[q4];
                            dst[q4] = make_float4(v[q4*4+0] + xv.x, v[q4*4+1] + xv.y,
                                                  v[q4*4+2] + xv.z, v[q4*4+3] + xv.w);
                        }
                    } else {
                        float4* dst = (float4*)(Cf + (size_t)gm * ldc + gn0);
#pragma unroll
                        for (int q4 = 0; q4 < 8; q4++)
                            dst[q4] = make_float4(v[q4*4], v[q4*4+1], v[q4*4+2], v[q4*4+3]);
                    }
                } else {
#pragma unroll
                    for (int j = 0; j < 32; j++) {
                        int gn = gn0 + j;
                        if (gn < Nstore) {
                            float t = v[j];
                            if (EPI == 3) t += xres[(size_t)gm * DREAL + gn];
                            Cf[(size_t)gm * ldc + gn] = t;
                        }
                    }
                }
            } else {  // bf16 outputs
                if (full) {
                    uint32_t pk[16];
#pragma unroll
                    for (int p = 0; p < 16; p++) {
                        __nv_bfloat162 h2 = __floats2bfloat162_rn(v[2*p], v[2*p+1]);
                        pk[p] = *(uint32_t*)&h2;
                    }
                    uint4* dst = (uint4*)(Cb + (size_t)gm * ldc + gn0);
#pragma unroll
                    for (int q4 = 0; q4 < 4; q4++)
                        dst[q4] = make_uint4(pk[q4*4], pk[q4*4+1], pk[q4*4+2], pk[q4*4+3]);
                } else {
#pragma unroll
                    for (int j = 0; j < 32; j++) {
                        int gn = gn0 + j;
                        if (gn < Nstore)
                            Cb[(size_t)gm * ldc + gn] = __float2bfloat16(v[j]);
                    }
                }
            }
        }
        TC_FENCE_BEFORE();
    }
    __syncthreads();
    if (wid == 0) TC_DEALLOC(tmem, 256);

#else
    // ------------------------------------------------------------------
    // WMMA fallback body (compute_103 pass) — 2-stage cp.async, BK=32
    // stage s: As @ s*30720 (256x40 bf16), Bs @ s*30720+20480 (128x40)
    // ------------------------------------------------------------------
    using namespace nvcuda;
    const int lane = tid & 31;
    const uint32_t smb = smem_u32(dsm_raw);
    __nv_bfloat16* AsP[2] = {(__nv_bfloat16*)dsm_raw,
                             (__nv_bfloat16*)(dsm_raw + 30720)};
    __nv_bfloat16* BsP[2] = {(__nv_bfloat16*)(dsm_raw + 20480),
                             (__nv_bfloat16*)(dsm_raw + 30720 + 20480)};
    float* stage = (float*)(dsm_raw + 61440);

    const int wm = (wid & 3) * 64;
    const int wn = (wid >> 2) * 64;
    const size_t ldab = (size_t)lda * 2, ldbb = (size_t)ldb * 2;
    const char* Abase = (const char*)(Ag + (size_t)m0 * lda);
    const char* Bbase = (const char*)(Bg + (size_t)n0 * ldb);

    wmma::fragment<wmma::accumulator, 16, 16, 16, float> acc[4][4];
#pragma unroll
    for (int i = 0; i < 4; i++)
#pragma unroll
        for (int j = 0; j < 4; j++) wmma::fill_fragment(acc[i][j], 0.0f);

    const int nc = K >> 5;
    // issue loads for chunk `cc` into stage `s`
    auto issue = [&](int cc, int s) {
        const uint32_t sa = smb + s * 30720;
        const uint32_t sb = sa + 20480;
        const char* Ab = Abase + (size_t)cc * 64;  // 32 bf16 = 64 bytes
        const char* Bb = Bbase + (size_t)cc * 64;
#pragma unroll
        for (int i = 0; i < 4; i++) {              // A: 256 rows x 64B
            int cid = tid + i * 256;
            int r = cid >> 2, cb = (cid & 3) << 4;
            CP_ASYNC16(sa + r * 80 + cb, Ab + (size_t)r * ldab + cb);
        }
#pragma unroll
        for (int i = 0; i < 2; i++) {              // B: 128 rows x 64B
            int cid = tid + i * 256;
            int r = cid >> 2, cb = (cid & 3) << 4;
            CP_ASYNC16(sb + r * 80 + cb, Bb + (size_t)r * ldbb + cb);
        }
    };

    issue(0, 0);
    CP_COMMIT();
    for (int c = 0; c < nc; c++) {
        if (c + 1 < nc) issue(c + 1, (c + 1) & 1);
        CP_COMMIT();
        CP_WAIT(1);
        __syncthreads();
        const __nv_bfloat16* As = AsP[c & 1];
        const __nv_bfloat16* Bs = BsP[c & 1];
#pragma unroll
        for (int kk = 0; kk < 32; kk += 16) {
            wmma::fragment<wmma::matrix_a, 16, 16, 16, __nv_bfloat16, wmma::row_major> af[4];
            wmma::fragment<wmma::matrix_b, 16, 16, 16, __nv_bfloat16, wmma::col_major> bf[4];
#pragma unroll
            for (int i = 0; i < 4; i++)
                wmma::load_matrix_sync(af[i], As + (size_t)(wm + i * 16) * 40 + kk, 40);
#pragma unroll
            for (int j = 0; j < 4; j++)
                wmma::load_matrix_sync(bf[j], Bs + (size_t)(wn + j * 16) * 40 + kk, 40);
#pragma unroll
            for (int i = 0; i < 4; i++)
#pragma unroll
                for (int j = 0; j < 4; j++)
                    wmma::mma_sync(acc[i][j], af[i], bf[j], acc[i][j]);
        }
        __syncthreads();
    }

    float* st = stage + wid * 256;
    float* Cf = (float*)Cv + z * sC;
    __nv_bfloat16* Cb = (__nv_bfloat16*)Cv + z * sC;
#pragma unroll
    for (int i = 0; i < 4; i++) {
#pragma unroll
        for (int j = 0; j < 4; j++) {
            wmma::store_matrix_sync(st, acc[i][j], 16, wmma::mem_row_major);
            __syncwarp();
#pragma unroll
            for (int e = lane; e < 256; e += 32) {
                int r = e >> 4, c = e & 15;
                int gm = m0 + wm + i * 16 + r;
                int gn = n0 + wn + j * 16 + c;
                if (gn < Nstore) {
                    float val = st[e];
                    if (EPI == 0) {
                        Cf[(size_t)gm * ldc + gn] = val;
                    } else if (EPI == 1) {
                        float b = (gn < nbias) ? bias[gn] : 0.0f;
                        Cb[(size_t)gm * ldc + gn] = __float2bfloat16((val + b) * alpha);
                    } else if (EPI == 2) {
                        float b = (gn < nbias) ? bias[gn] : 0.0f;
                        float t = val + b;
                        float g = 0.5f * t * (1.0f + erff(t * 0.70710678118654752f));
                        Cb[(size_t)gm * ldc + gn] = __float2bfloat16(g);
                    } else if (EPI == 3) {
                        float b = (gn < nbias) ? bias[gn] : 0.0f;
                        Cf[(size_t)gm * ldc + gn] =
                            val + b + xres[(size_t)gm * DREAL + gn];
                    } else {
                        Cb[(size_t)gm * ldc + gn] = __float2bfloat16(val);
                    }
                }
            }
            __syncwarp();
        }
    }
#endif  // USE_TCGEN05
}

// ============================================================================
// fp32 -> bf16 with zero padding
// ============================================================================
__global__ void pad_cast_kernel(const float* __restrict__ src,
                                __nv_bfloat16* __restrict__ dst,
                                int R, int C, int Rp, int Cp) {
    size_t idx = (size_t)blockIdx.x * 256 + threadIdx.x;
    size_t total = (size_t)Rp * Cp;
    if (idx >= total) return;
    int r = (int)(idx / Cp), c = (int)(idx % Cp);
    float v = (r < R && c < C) ? src[(size_t)r * C + c] : 0.0f;
    dst[idx] = __float2bfloat16(v);
}

// ============================================================================
// per-batch transpose: v[z][n][d] (DP wide) -> vt[z][d][n] (NPOS wide)
// ============================================================================
__global__ __launch_bounds__(256)
void transpose_kernel(const __nv_bfloat16* __restrict__ v,
                      __nv_bfloat16* __restrict__ vt) {
    __shared__ __nv_bfloat16 t[32][33];
    const int z = blockIdx.z;
    const int nb = blockIdx.x * 32, db = blockIdx.y * 32;
    const int tx = threadIdx.x & 31, ty = threadIdx.x >> 5;
    const __nv_bfloat16* vsrc = v + (size_t)z * NPOS * DP;
    __nv_bfloat16* vdst = vt + (size_t)z * DP * NPOS;
#pragma unroll
    for (int i = 0; i < 4; i++)
        t[ty + i * 8][tx] = vsrc[(size_t)(nb + ty + i * 8) * DP + db + tx];
    __syncthreads();
#pragma unroll
    for (int i = 0; i < 4; i++)
        vdst[(size_t)(db + ty + i * 8) * NPOS + nb + tx] = t[tx][ty + i * 8];
}

// ============================================================================
// Row softmax: S fp32 [rows, 2048] -> P bf16
// ============================================================================
__global__ __launch_bounds__(256)
void softmax_kernel(const float* __restrict__ S, __nv_bfloat16* __restrict__ P) {
    const size_t row = blockIdx.x;
    const float* s = S + row * (size_t)NPOS;
    __nv_bfloat16* p = P + row * (size_t)NPOS;
    const int tid = threadIdx.x, wid = tid >> 5, lane = tid & 31;
    float v[8], mx = -1e30f;
#pragma unroll
    for (int i = 0; i < 8; i++) { v[i] = s[tid + i * 256]; mx = fmaxf(mx, v[i]); }
    __shared__ float rm[8], rs[8];
#pragma unroll
    for (int o = 16; o > 0; o >>= 1) mx = fmaxf(mx, __shfl_xor_sync(~0u, mx, o));
    if (lane == 0) rm[wid] = mx;
    __syncthreads();
    float bm = rm[0];
#pragma unroll
    for (int i = 1; i < 8; i++) bm = fmaxf(bm, rm[i]);
    float sum = 0.0f;
#pragma unroll
    for (int i = 0; i < 8; i++) { v[i] = __expf(v[i] - bm); sum += v[i]; }
#pragma unroll
    for (int o = 16; o > 0; o >>= 1) sum += __shfl_xor_sync(~0u, sum, o);
    if (lane == 0) rs[wid] = sum;
    __syncthreads();
    float tot = 0.0f;
#pragma unroll
    for (int i = 0; i < 8; i++) tot += rs[i];
    float inv = 1.0f / tot;
#pragma unroll
    for (int i = 0; i < 8; i++) p[tid + i * 256] = __float2bfloat16(v[i] * inv);
}

// ============================================================================
// launch
// ============================================================================
static inline void pad_cast(const float* src, void* dst, int R, int C, int Rp, int Cp) {
    size_t total = (size_t)Rp * Cp;
    pad_cast_kernel<<<(int)((total + 255) / 256), 256>>>(src, (__nv_bfloat16*)dst, R, C, Rp, Cp);
}

extern "C" void kernel_launch(void* const* d_in, const int* in_sizes, int n_in,
                              void* d_out, int out_size) {
    const float* x  = (const float*)d_in[0];
    const float* Wq = (const float*)d_in[1];
    const float* bq = (const float*)d_in[2];
    const float* Wk = (const float*)d_in[3];
    const float* bk = (const float*)d_in[4];
    const float* Wv = (const float*)d_in[5];
    const float* bv = (const float*)d_in[6];
    const float* We = (const float*)d_in[7];
    const float* be = (const float*)d_in[8];
    const float* Wo = (const float*)d_in[9];
    const float* bo = (const float*)d_in[10];

    void *p_xb, *p_q, *p_k, *p_v, *p_vt, *p_attn, *p_h, *p_S, *p_P;
    void *p_Wq, *p_Wk, *p_Wv, *p_We, *p_Wo;
    cudaGetSymbolAddress(&p_xb, g_xb);
    cudaGetSymbolAddress(&p_q, g_q);
    cudaGetSymbolAddress(&p_k, g_k);
    cudaGetSymbolAddress(&p_v, g_v);
    cudaGetSymbolAddress(&p_vt, g_vt);
    cudaGetSymbolAddress(&p_attn, g_attn);
    cudaGetSymbolAddress(&p_h, g_h);
    cudaGetSymbolAddress(&p_S, g_S);
    cudaGetSymbolAddress(&p_P, g_P);
    cudaGetSymbolAddress(&p_Wq, g_Wq);
    cudaGetSymbolAddress(&p_Wk, g_Wk);
    cudaGetSymbolAddress(&p_Wv, g_Wv);
    cudaGetSymbolAddress(&p_We, g_We);
    cudaGetSymbolAddress(&p_Wo, g_Wo);

    cudaFuncSetAttribute(tc_gemm<0>, cudaFuncAttributeMaxDynamicSharedMemorySize, SMEM_BYTES);
    cudaFuncSetAttribute(tc_gemm<1>, cudaFuncAttributeMaxDynamicSharedMemorySize, SMEM_BYTES);
    cudaFuncSetAttribute(tc_gemm<2>, cudaFuncAttributeMaxDynamicSharedMemorySize, SMEM_BYTES);
    cudaFuncSetAttribute(tc_gemm<3>, cudaFuncAttributeMaxDynamicSharedMemorySize, SMEM_BYTES);
    cudaFuncSetAttribute(tc_gemm<4>, cudaFuncAttributeMaxDynamicSharedMemorySize, SMEM_BYTES);

    // 1) casts + padding (padded regions exact zero)
    pad_cast(x,  p_xb, MROWS, DREAL, MROWS, DP);
    pad_cast(Wq, p_Wq, DREAL, DREAL, DP, DP);
    pad_cast(Wk, p_Wk, DREAL, DREAL, DP, DP);
    pad_cast(Wv, p_Wv, DREAL, DREAL, DP, DP);
    pad_cast(We, p_We, HREAL, DREAL, HP, DP);
    pad_cast(Wo, p_Wo, DREAL, HREAL, DP, HP);

    const float qscale = 1.0f / sqrtf((float)DREAL);
    dim3 blk(256);

    // 2) q/k/v projections: [16384,1152] = xb @ W^T + b
    {
        dim3 grid(DP / 128, MROWS / 256, 1);  // (9,64)
        tc_gemm<1><<<grid, blk, SMEM_BYTES>>>(
            (const __nv_bfloat16*)p_xb, (const __nv_bfloat16*)p_Wq, p_q,
            DP, DP, DP, DP, DP, bq, DREAL, qscale, nullptr, 0, 0, 0);
        tc_gemm<1><<<grid, blk, SMEM_BYTES>>>(
            (const __nv_bfloat16*)p_xb, (const __nv_bfloat16*)p_Wk, p_k,
            DP, DP, DP, DP, DP, bk, DREAL, 1.0f, nullptr, 0, 0, 0);
        tc_gemm<1><<<grid, blk, SMEM_BYTES>>>(
            (const __nv_bfloat16*)p_xb, (const __nv_bfloat16*)p_Wv, p_v,
            DP, DP, DP, DP, DP, bv, DREAL, 1.0f, nullptr, 0, 0, 0);
    }

    // 3) scores: per batch, S = q @ k^T (scale folded into q)
    {
        dim3 grid(NPOS / 128, NPOS / 256, NBATCH);  // (16,8,8)
        tc_gemm<0><<<grid, blk, SMEM_BYTES>>>(
            (const __nv_bfloat16*)p_q, (const __nv_bfloat16*)p_k, p_S,
            DP, DP, DP, NPOS, NPOS, nullptr, 0, 1.0f, nullptr,
            (size_t)NPOS * DP, (size_t)NPOS * DP, (size_t)NPOS * NPOS);
    }

    // 4) softmax rows
    softmax_kernel<<<NBATCH * NPOS, 256>>>((const float*)p_S, (__nv_bfloat16*)p_P);

    // 5) transpose V per batch: v[n,d] -> vt[d,n]
    {
        dim3 grid(NPOS / 32, DP / 32, NBATCH);  // (64,36,8)
        transpose_kernel<<<grid, blk>>>((const __nv_bfloat16*)p_v,
                                        (__nv_bfloat16*)p_vt);
    }

    // 6) attn = P @ V = P @ (Vt)^T
    {
        dim3 grid(DP / 128, NPOS / 256, NBATCH);  // (9,8,8)
        tc_gemm<4><<<grid, blk, SMEM_BYTES>>>(
            (const __nv_bfloat16*)p_P, (const __nv_bfloat16*)p_vt, p_attn,
            NPOS, NPOS, NPOS, DP, DP, nullptr, 0, 1.0f, nullptr,
            (size_t)NPOS * NPOS, (size_t)DP * NPOS, (size_t)NPOS * DP);
    }

    // 7) h = gelu(attn @ We^T + be)
    {
        dim3 grid(HP / 128, MROWS / 256, 1);  // (33,64)
        tc_gemm<2><<<grid, blk, SMEM_BYTES>>>(
            (const __nv_bfloat16*)p_attn, (const __nv_bfloat16*)p_We, p_h,
            DP, DP, DP, HP, HP, be, HREAL, 1.0f, nullptr, 0, 0, 0);
    }

    // 8) out = h @ Wo^T + bo + x  (fp32, width 1028 guarded)
    {
        dim3 grid((DREAL + 127) / 128, MROWS / 256, 1);  // (9,64)
        tc_gemm<3><<<grid, blk, SMEM_BYTES>>>(
            (const __nv_bfloat16*)p_h, (const __nv_bfloat16*)p_Wo, d_out,
            HP, HP, HP, DREAL, DREAL, bo, DREAL, 1.0f, x, 0, 0, 0);
    }
}

// round 10
// speedup vs baseline: 2.7952x; 1.1041x over previous
#include <cuda_runtime.h>
#include <cuda_bf16.h>
#include <mma.h>
#include <cstdint>
#include <math.h>

// ============================================================================
// Dimensions:  B=8, N=2048, D=1028 -> pad 1152 (9*128), H=4112 -> pad 4224
// (33*128). M = B*N = 16384. All tiles exact; padded regions are exact zeros.
// ============================================================================
#define MROWS  16384
#define NPOS   2048
#define NBATCH 8
#define DREAL  1028
#define DP     1152
#define HREAL  4112
#define HP     4224

#if defined(__CUDA_ARCH_FEAT_SM103_ALL) || defined(__CUDA_ARCH_FEAT_SM100_ALL) || defined(__CUDA_ARCH_SPECIFIC__)
#define USE_TCGEN05 1
#else
#define USE_TCGEN05 0
#endif

// ---- scratch (device globals; no runtime allocation allowed) ----
__device__ __nv_bfloat16 g_xb  [(size_t)MROWS * DP];
__device__ __nv_bfloat16 g_q   [(size_t)MROWS * DP];
__device__ __nv_bfloat16 g_k   [(size_t)MROWS * DP];
__device__ __nv_bfloat16 g_v   [(size_t)MROWS * DP];
__device__ __nv_bfloat16 g_vt  [(size_t)NBATCH * DP * NPOS];
__device__ __nv_bfloat16 g_attn[(size_t)MROWS * DP];
__device__ __nv_bfloat16 g_h   [(size_t)MROWS * HP];
__device__ __nv_bfloat16 g_S   [(size_t)NBATCH * NPOS * NPOS];
__device__ __nv_bfloat16 g_P   [(size_t)NBATCH * NPOS * NPOS];
__device__ __nv_bfloat16 g_Wq  [(size_t)DP * DP];
__device__ __nv_bfloat16 g_Wk  [(size_t)DP * DP];
__device__ __nv_bfloat16 g_Wv  [(size_t)DP * DP];
__device__ __nv_bfloat16 g_We  [(size_t)HP * DP];
__device__ __nv_bfloat16 g_Wo  [(size_t)DP * HP];

// ============================================================================
// PTX helpers
// ============================================================================
__device__ __forceinline__ uint32_t smem_u32(const void* p) {
    uint32_t a;
    asm("{ .reg .u64 t; cvta.to.shared.u64 t, %1; cvt.u32.u64 %0, t; }"
        : "=r"(a) : "l"(p));
    return a;
}
#define CP_ASYNC16(dst, src) \
    asm volatile("cp.async.cg.shared.global [%0], [%1], 16;" \
                 :: "r"(dst), "l"(src) : "memory")
#define CP_COMMIT() asm volatile("cp.async.commit_group;" ::: "memory")
#define CP_WAIT(n)  asm volatile("cp.async.wait_group %0;" :: "n"(n) : "memory")

#if USE_TCGEN05
__device__ __forceinline__ uint32_t elect_one() {
    uint32_t p;
    asm volatile("{\n\t.reg .pred p;\n\telect.sync _|p, 0xFFFFFFFF;\n\t"
                 "selp.b32 %0, 1, 0, p;\n\t}" : "=r"(p));
    return p;
}
#define MBAR_INIT(addr, cnt) \
    asm volatile("mbarrier.init.shared.b64 [%0], %1;" :: "r"(addr), "r"(cnt) : "memory")
#define MBAR_WAIT(addr, par) do {                                              \
    uint32_t _m = (addr), _p = (par), _d;                                      \
    asm volatile("{\n\t.reg .pred p;\n\t"                                      \
        "mbarrier.try_wait.parity.acquire.cta.shared::cta.b64 p, [%1], %2;\n\t"\
        "selp.b32 %0, 1, 0, p;\n\t}" : "=r"(_d) : "r"(_m), "r"(_p) : "memory");\
    if (!_d) {                                                                 \
        asm volatile("{\n\t.reg .pred P1;\n\t"                                 \
        "W_%=:\n\t"                                                            \
        "mbarrier.try_wait.parity.acquire.cta.shared::cta.b64 P1, [%0], %1, 0x989680;\n\t" \
        "@P1 bra.uni D_%=;\n\t"                                                \
        "bra.uni W_%=;\n\t"                                                    \
        "D_%=:\n\t}" :: "r"(_m), "r"(_p) : "memory");                          \
    }                                                                          \
} while (0)
#define TC_ALLOC(smem_addr, n) \
    asm volatile("tcgen05.alloc.cta_group::1.sync.aligned.shared::cta.b32 [%0], %1;" \
                 :: "r"(smem_addr), "r"((uint32_t)(n)) : "memory")
#define TC_RELINQ() \
    asm volatile("tcgen05.relinquish_alloc_permit.cta_group::1.sync.aligned;")
#define TC_DEALLOC(tmem, n) \
    asm volatile("tcgen05.dealloc.cta_group::1.sync.aligned.b32 %0, %1;" \
                 :: "r"(tmem), "r"((uint32_t)(n)))
#define TC_COMMIT(mbar) \
    asm volatile("tcgen05.commit.cta_group::1.mbarrier::arrive::one.shared::cluster.b64 [%0];" \
                 :: "r"(mbar) : "memory")
#define TC_FENCE_AFTER()  asm volatile("tcgen05.fence::after_thread_sync;" ::: "memory")
#define TC_FENCE_BEFORE() asm volatile("tcgen05.fence::before_thread_sync;" ::: "memory")
#define FENCE_ASYNC_SHARED() asm volatile("fence.proxy.async.shared::cta;" ::: "memory")
#define TC_WAIT_LD() asm volatile("tcgen05.wait::ld.sync.aligned;" ::: "memory")

#define TC_LD_X32(r, addr)                                                     \
    asm volatile("tcgen05.ld.sync.aligned.32x32b.x32.b32 "                     \
        "{%0, %1, %2, %3, %4, %5, %6, %7, %8, %9, %10, %11, %12, %13, %14, %15,"\
        " %16, %17, %18, %19, %20, %21, %22, %23, %24, %25, %26, %27, %28, %29, %30, %31}, [%32];" \
        : "=r"((r)[0]), "=r"((r)[1]), "=r"((r)[2]), "=r"((r)[3]),              \
          "=r"((r)[4]), "=r"((r)[5]), "=r"((r)[6]), "=r"((r)[7]),              \
          "=r"((r)[8]), "=r"((r)[9]), "=r"((r)[10]), "=r"((r)[11]),            \
          "=r"((r)[12]), "=r"((r)[13]), "=r"((r)[14]), "=r"((r)[15]),          \
          "=r"((r)[16]), "=r"((r)[17]), "=r"((r)[18]), "=r"((r)[19]),          \
          "=r"((r)[20]), "=r"((r)[21]), "=r"((r)[22]), "=r"((r)[23]),          \
          "=r"((r)[24]), "=r"((r)[25]), "=r"((r)[26]), "=r"((r)[27]),          \
          "=r"((r)[28]), "=r"((r)[29]), "=r"((r)[30]), "=r"((r)[31])           \
        : "r"(addr))

// bf16 SS MMA, cta_group::1, kind::f16, fp32 accum
__device__ __forceinline__ void mma_ss(uint32_t d, uint64_t ad, uint64_t bd,
                                       uint32_t idesc, uint32_t en) {
    asm volatile(
        "{\n\t.reg .pred p;\n\tsetp.ne.u32 p, %5, 0;\n\t"
        "tcgen05.mma.cta_group::1.kind::f16 [%0], %1, %2, %3, {%4, %4, %4, %4}, p;\n\t}"
        :: "r"(d), "l"(ad), "l"(bd), "r"(idesc), "r"(0u), "r"(en) : "memory");
}
// K-major SW128 descriptor (validated: LBO=1, SBO=64, layout=2, version=1)
__device__ __forceinline__ uint64_t mk_desc(uint32_t addr) {
    return ((uint64_t)2 << 61) | ((uint64_t)1 << 46) | ((uint64_t)64 << 32) |
           ((uint64_t)1 << 16) | (uint64_t)((addr >> 4) & 0x3FFF);
}
// idesc: F32 accum, BF16 A/B, M=128, N=128 (validated base with N field -> 128)
#define TC_IDESC 0x8200490u
#endif  // USE_TCGEN05

// ============================================================================
// GEMM:  C[M,N] = A[M,K] * B[N,K]^T  (bf16 row-major, fp32 acc)
// CTA tile 256x128, 256 threads.
//   sm_103a : tcgen05, BK=64, 4-stage cp.async (SW128), MMA lag 2, TMEM 256 col
//   generic : WMMA fallback, 2-stage cp.async, 8 warps of 64x64
// EPI: 0 fp32 | 1 bf16((v+b)*alpha) | 2 bf16(gelu(v+b)) | 3 fp32(v+b+x) | 4 bf16(v)
// ============================================================================
#define MMALAG 2
#define SMEM_BYTES (4 * 49152 + 1024)

template <int EPI>
__global__ __launch_bounds__(256)
void tc_gemm(const __nv_bfloat16* __restrict__ Ag,
             const __nv_bfloat16* __restrict__ Bg,
             void* __restrict__ Cv,
             int K, int lda, int ldb, int ldc, int Nstore,
             const float* __restrict__ bias, int nbias, float alpha,
             const float* __restrict__ xres,
             size_t sA, size_t sB, size_t sC) {
    extern __shared__ char dsm_raw[];
    const int tid = threadIdx.x;
    const int wid = tid >> 5;
    const int z = blockIdx.z;
    Ag += z * sA;
    Bg += z * sB;
    const int m0 = blockIdx.y * 256;
    const int n0 = blockIdx.x * 128;

#if USE_TCGEN05
    // ------------------------------------------------------------------
    // tcgen05 body — 4-stage cp.async pipeline, MMA issue lag 2
    // ------------------------------------------------------------------
    char* smem = (char*)(((uintptr_t)dsm_raw + 1023) & ~(uintptr_t)1023);
    __shared__ __align__(16) unsigned long long mbar_store[4];
    __shared__ uint32_t tmem_store[1];

    const uint32_t smb = smem_u32(smem);
    uint32_t slotA[4], slotB[4];
    uint64_t dAh[4][2], dBv[4];
#pragma unroll
    for (int s = 0; s < 4; s++) {
        slotA[s] = smb + s * 49152;
        slotB[s] = slotA[s] + 32768;
        dAh[s][0] = mk_desc(slotA[s]);
        dAh[s][1] = mk_desc(slotA[s] + 16384);
        dBv[s] = mk_desc(slotB[s]);
    }
    uint32_t mb[4];
#pragma unroll
    for (int s = 0; s < 4; s++) mb[s] = smem_u32(&mbar_store[s]);
    const uint32_t tps = smem_u32(&tmem_store[0]);

    if (wid == 0) { TC_ALLOC(tps, 256); TC_RELINQ(); }
    if (tid == 0) {
#pragma unroll
        for (int s = 0; s < 4; s++) MBAR_INIT(mb[s], 1);
    }
    __syncthreads();
    uint32_t tmem;
    asm volatile("ld.shared.b32 %0, [%1];" : "=r"(tmem) : "r"(tps));

    const int nc = K >> 6;
    const size_t ldab = (size_t)lda * 2, ldbb = (size_t)ldb * 2;
    const char* Abase = (const char*)(Ag + (size_t)m0 * lda);
    const char* Bbase = (const char*)(Bg + (size_t)n0 * ldb);
    int phase[4] = {0, 0, 0, 0};

    for (int c = 0; c < nc + MMALAG; c++) {
        if (c < nc) {
            const int s = c & 3;
            if (c >= 4) { MBAR_WAIT(mb[s], phase[s]); phase[s] ^= 1; }
            const char* Ab = Abase + (size_t)c * 128;  // 64 bf16 = 128 bytes
            const char* Bb = Bbase + (size_t)c * 128;
            const uint32_t sa = slotA[s], sb = slotB[s];
#pragma unroll
            for (int i = 0; i < 8; i++) {           // A: 256 rows x 128B
                int cid = tid + i * 256;
                int r = cid >> 3, cb = (cid & 7) << 4;
                uint32_t off = ((r & 127) << 7) + cb;
                uint32_t sw = off ^ ((off >> 3) & 0x70);
                CP_ASYNC16(sa + ((r >> 7) << 14) + sw, Ab + (size_t)r * ldab + cb);
            }
#pragma unroll
            for (int i = 0; i < 4; i++) {           // B: 128 rows x 128B
                int cid = tid + i * 256;
                int r = cid >> 3, cb = (cid & 7) << 4;
                uint32_t off = (r << 7) + cb;
                uint32_t sw = off ^ ((off >> 3) & 0x70);
                CP_ASYNC16(sb + sw, Bb + (size_t)r * ldbb + cb);
            }
        }
        CP_COMMIT();   // one group per iteration (possibly empty in tail)
        if (c >= MMALAG) {
            CP_WAIT(MMALAG);       // group (c-MMALAG) complete for this thread
            FENCE_ASYNC_SHARED();  // writer-side generic->async visibility
            __syncthreads();       // all threads' fills visible
            const int cc = c - MMALAG, s2 = cc & 3;
            if (wid == 0) {
                if (elect_one()) {
#pragma unroll
                    for (int st = 0; st < 4; st++) {
#pragma unroll
                        for (int h = 0; h < 2; h++) {
                            mma_ss(tmem + h * 128, dAh[s2][h] + st * 2,
                                   dBv[s2] + st * 2, TC_IDESC,
                                   (cc > 0 || st > 0) ? 1u : 0u);
                        }
                    }
                    TC_COMMIT(mb[s2]);
                }
            }
        }
    }
#pragma unroll
    for (int s = 0; s < 4; s++) MBAR_WAIT(mb[s], phase[s]);
    TC_FENCE_AFTER();

    // ---- epilogue: warp-group wg = M-half (D column offset), subpartition
    //      sp = rows. Each warp: 32 rows x 128 cols. ----
    {
        const int wg = wid >> 2, sp = wid & 3, lane = tid & 31;
        const int gm = m0 + wg * 128 + sp * 32 + lane;
        float* Cf = (float*)Cv + z * sC;
        __nv_bfloat16* Cb = (__nv_bfloat16*)Cv + z * sC;
#pragma unroll
        for (int b = 0; b < 4; b++) {
            const int gn0 = n0 + b * 32;
            if (gn0 >= Nstore) continue;   // uniform across warp
            uint32_t regs[32];
            TC_LD_X32(regs, tmem + wg * 128 + b * 32);
            TC_WAIT_LD();
            float v[32];
#pragma unroll
            for (int j = 0; j < 32; j++) {
                float t = __uint_as_float(regs[j]);
                const int gn = gn0 + j;
                if (EPI == 1) {
                    float bb = (gn < nbias) ? bias[gn] : 0.0f;
                    t = (t + bb) * alpha;
                } else if (EPI == 2) {
                    float bb = (gn < nbias) ? bias[gn] : 0.0f;
                    float u = t + bb;
                    t = 0.5f * u * (1.0f + erff(u * 0.70710678118654752f));
                } else if (EPI == 3) {
                    float bb = (gn < nbias) ? bias[gn] : 0.0f;
                    t = t + bb;   // residual added below
                }
                v[j] = t;
            }
            const bool full = (gn0 + 32 <= Nstore);
            if (EPI == 0 || EPI == 3) {
                if (full) {
                    if (EPI == 3) {
                        const float4* xr = (const float4*)(xres + (size_t)gm * DREAL + gn0);
                        float4* dst = (float4*)(Cf + (size_t)gm * ldc + gn0);
#pragma unroll
                        for (int q4 = 0; q4 < 8; q4++) {
                            float4 xv = xr[q4];
                            dst[q4] = make_float4(v[q4*4+0] + xv.x, v[q4*4+1] + xv.y,
                                                  v[q4*4+2] + xv.z, v[q4*4+3] + xv.w);
                        }
                    } else {
                        float4* dst = (float4*)(Cf + (size_t)gm * ldc + gn0);
#pragma unroll
                        for (int q4 = 0; q4 < 8; q4++)
                            dst[q4] = make_float4(v[q4*4], v[q4*4+1], v[q4*4+2], v[q4*4+3]);
                    }
                } else {
#pragma unroll
                    for (int j = 0; j < 32; j++) {
                        int gn = gn0 + j;
                        if (gn < Nstore) {
                            float t = v[j];
                            if (EPI == 3) t += xres[(size_t)gm * DREAL + gn];
                            Cf[(size_t)gm * ldc + gn] = t;
                        }
                    }
                }
            } else {  // bf16 outputs
                if (full) {
                    uint32_t pk[16];
#pragma unroll
                    for (int p = 0; p < 16; p++) {
                        __nv_bfloat162 h2 = __floats2bfloat162_rn(v[2*p], v[2*p+1]);
                        pk[p] = *(uint32_t*)&h2;
                    }
                    uint4* dst = (uint4*)(Cb + (size_t)gm * ldc + gn0);
#pragma unroll
                    for (int q4 = 0; q4 < 4; q4++)
                        dst[q4] = make_uint4(pk[q4*4], pk[q4*4+1], pk[q4*4+2], pk[q4*4+3]);
                } else {
#pragma unroll
                    for (int j = 0; j < 32; j++) {
                        int gn = gn0 + j;
                        if (gn < Nstore)
                            Cb[(size_t)gm * ldc + gn] = __float2bfloat16(v[j]);
                    }
                }
            }
        }
        TC_FENCE_BEFORE();
    }
    __syncthreads();
    if (wid == 0) TC_DEALLOC(tmem, 256);

#else
    // ------------------------------------------------------------------
    // WMMA fallback body (compute_103 pass) — 2-stage cp.async, BK=32
    // ------------------------------------------------------------------
    using namespace nvcuda;
    const int lane = tid & 31;
    const uint32_t smb = smem_u32(dsm_raw);
    __nv_bfloat16* AsP[2] = {(__nv_bfloat16*)dsm_raw,
                             (__nv_bfloat16*)(dsm_raw + 30720)};
    __nv_bfloat16* BsP[2] = {(__nv_bfloat16*)(dsm_raw + 20480),
                             (__nv_bfloat16*)(dsm_raw + 30720 + 20480)};
    float* stage = (float*)(dsm_raw + 61440);

    const int wm = (wid & 3) * 64;
    const int wn = (wid >> 2) * 64;
    const size_t ldab = (size_t)lda * 2, ldbb = (size_t)ldb * 2;
    const char* Abase = (const char*)(Ag + (size_t)m0 * lda);
    const char* Bbase = (const char*)(Bg + (size_t)n0 * ldb);

    wmma::fragment<wmma::accumulator, 16, 16, 16, float> acc[4][4];
#pragma unroll
    for (int i = 0; i < 4; i++)
#pragma unroll
        for (int j = 0; j < 4; j++) wmma::fill_fragment(acc[i][j], 0.0f);

    const int nc = K >> 5;
    auto issue = [&](int cc, int s) {
        const uint32_t sa = smb + s * 30720;
        const uint32_t sb = sa + 20480;
        const char* Ab = Abase + (size_t)cc * 64;
        const char* Bb = Bbase + (size_t)cc * 64;
#pragma unroll
        for (int i = 0; i < 4; i++) {
            int cid = tid + i * 256;
            int r = cid >> 2, cb = (cid & 3) << 4;
            CP_ASYNC16(sa + r * 80 + cb, Ab + (size_t)r * ldab + cb);
        }
#pragma unroll
        for (int i = 0; i < 2; i++) {
            int cid = tid + i * 256;
            int r = cid >> 2, cb = (cid & 3) << 4;
            CP_ASYNC16(sb + r * 80 + cb, Bb + (size_t)r * ldbb + cb);
        }
    };

    issue(0, 0);
    CP_COMMIT();
    for (int c = 0; c < nc; c++) {
        if (c + 1 < nc) issue(c + 1, (c + 1) & 1);
        CP_COMMIT();
        CP_WAIT(1);
        __syncthreads();
        const __nv_bfloat16* As = AsP[c & 1];
        const __nv_bfloat16* Bs = BsP[c & 1];
#pragma unroll
        for (int kk = 0; kk < 32; kk += 16) {
            wmma::fragment<wmma::matrix_a, 16, 16, 16, __nv_bfloat16, wmma::row_major> af[4];
            wmma::fragment<wmma::matrix_b, 16, 16, 16, __nv_bfloat16, wmma::col_major> bf[4];
#pragma unroll
            for (int i = 0; i < 4; i++)
                wmma::load_matrix_sync(af[i], As + (size_t)(wm + i * 16) * 40 + kk, 40);
#pragma unroll
            for (int j = 0; j < 4; j++)
                wmma::load_matrix_sync(bf[j], Bs + (size_t)(wn + j * 16) * 40 + kk, 40);
#pragma unroll
            for (int i = 0; i < 4; i++)
#pragma unroll
                for (int j = 0; j < 4; j++)
                    wmma::mma_sync(acc[i][j], af[i], bf[j], acc[i][j]);
        }
        __syncthreads();
    }

    float* st = stage + wid * 256;
    float* Cf = (float*)Cv + z * sC;
    __nv_bfloat16* Cb = (__nv_bfloat16*)Cv + z * sC;
#pragma unroll
    for (int i = 0; i < 4; i++) {
#pragma unroll
        for (int j = 0; j < 4; j++) {
            wmma::store_matrix_sync(st, acc[i][j], 16, wmma::mem_row_major);
            __syncwarp();
#pragma unroll
            for (int e = lane; e < 256; e += 32) {
                int r = e >> 4, cx = e & 15;
                int gm = m0 + wm + i * 16 + r;
                int gn = n0 + wn + j * 16 + cx;
                if (gn < Nstore) {
                    float val = st[e];
                    if (EPI == 0) {
                        Cf[(size_t)gm * ldc + gn] = val;
                    } else if (EPI == 1) {
                        float b = (gn < nbias) ? bias[gn] : 0.0f;
                        Cb[(size_t)gm * ldc + gn] = __float2bfloat16((val + b) * alpha);
                    } else if (EPI == 2) {
                        float b = (gn < nbias) ? bias[gn] : 0.0f;
                        float t = val + b;
                        float g = 0.5f * t * (1.0f + erff(t * 0.70710678118654752f));
                        Cb[(size_t)gm * ldc + gn] = __float2bfloat16(g);
                    } else if (EPI == 3) {
                        float b = (gn < nbias) ? bias[gn] : 0.0f;
                        Cf[(size_t)gm * ldc + gn] =
                            val + b + xres[(size_t)gm * DREAL + gn];
                    } else {
                        Cb[(size_t)gm * ldc + gn] = __float2bfloat16(val);
                    }
                }
            }
            __syncwarp();
        }
    }
#endif  // USE_TCGEN05
}

// ============================================================================
// fp32 -> bf16 with zero padding
// ============================================================================
__global__ void pad_cast_kernel(const float* __restrict__ src,
                                __nv_bfloat16* __restrict__ dst,
                                int R, int C, int Rp, int Cp) {
    size_t idx = (size_t)blockIdx.x * 256 + threadIdx.x;
    size_t total = (size_t)Rp * Cp;
    if (idx >= total) return;
    int r = (int)(idx / Cp), c = (int)(idx % Cp);
    float v = (r < R && c < C) ? src[(size_t)r * C + c] : 0.0f;
    dst[idx] = __float2bfloat16(v);
}

// ============================================================================
// per-batch transpose: v[z][n][d] (DP wide) -> vt[z][d][n] (NPOS wide)
// ============================================================================
__global__ __launch_bounds__(256)
void transpose_kernel(const __nv_bfloat16* __restrict__ v,
                      __nv_bfloat16* __restrict__ vt) {
    __shared__ __nv_bfloat16 t[32][33];
    const int z = blockIdx.z;
    const int nb = blockIdx.x * 32, db = blockIdx.y * 32;
    const int tx = threadIdx.x & 31, ty = threadIdx.x >> 5;
    const __nv_bfloat16* vsrc = v + (size_t)z * NPOS * DP;
    __nv_bfloat16* vdst = vt + (size_t)z * DP * NPOS;
#pragma unroll
    for (int i = 0; i < 4; i++)
        t[ty + i * 8][tx] = vsrc[(size_t)(nb + ty + i * 8) * DP + db + tx];
    __syncthreads();
#pragma unroll
    for (int i = 0; i < 4; i++)
        vdst[(size_t)(db + ty + i * 8) * NPOS + nb + tx] = t[tx][ty + i * 8];
}

// ============================================================================
// Row softmax: S bf16 [rows, 2048] -> P bf16
// ============================================================================
__global__ __launch_bounds__(256)
void softmax_kernel(const __nv_bfloat16* __restrict__ S,
                    __nv_bfloat16* __restrict__ P) {
    const size_t row = blockIdx.x;
    const __nv_bfloat16* s = S + row * (size_t)NPOS;
    __nv_bfloat16* p = P + row * (size_t)NPOS;
    const int tid = threadIdx.x, wid = tid >> 5, lane = tid & 31;
    float v[8], mx = -1e30f;
#pragma unroll
    for (int i = 0; i < 8; i++) {
        v[i] = __bfloat162float(s[tid + i * 256]);
        mx = fmaxf(mx, v[i]);
    }
    __shared__ float rm[8], rs[8];
#pragma unroll
    for (int o = 16; o > 0; o >>= 1) mx = fmaxf(mx, __shfl_xor_sync(~0u, mx, o));
    if (lane == 0) rm[wid] = mx;
    __syncthreads();
    float bm = rm[0];
#pragma unroll
    for (int i = 1; i < 8; i++) bm = fmaxf(bm, rm[i]);
    float sum = 0.0f;
#pragma unroll
    for (int i = 0; i < 8; i++) { v[i] = __expf(v[i] - bm); sum += v[i]; }
#pragma unroll
    for (int o = 16; o > 0; o >>= 1) sum += __shfl_xor_sync(~0u, sum, o);
    if (lane == 0) rs[wid] = sum;
    __syncthreads();
    float tot = 0.0f;
#pragma unroll
    for (int i = 0; i < 8; i++) tot += rs[i];
    float inv = 1.0f / tot;
#pragma unroll
    for (int i = 0; i < 8; i++) p[tid + i * 256] = __float2bfloat16(v[i] * inv);
}

// ============================================================================
// launch — ordered so the 6th launch is GEMM-q (ncu -s 5 -c 1 captures it)
// ============================================================================
static inline void pad_cast(const float* src, void* dst, int R, int C, int Rp, int Cp) {
    size_t total = (size_t)Rp * Cp;
    pad_cast_kernel<<<(int)((total + 255) / 256), 256>>>(src, (__nv_bfloat16*)dst, R, C, Rp, Cp);
}

extern "C" void kernel_launch(void* const* d_in, const int* in_sizes, int n_in,
                              void* d_out, int out_size) {
    const float* x  = (const float*)d_in[0];
    const float* Wq = (const float*)d_in[1];
    const float* bq = (const float*)d_in[2];
    const float* Wk = (const float*)d_in[3];
    const float* bk = (const float*)d_in[4];
    const float* Wv = (const float*)d_in[5];
    const float* bv = (const float*)d_in[6];
    const float* We = (const float*)d_in[7];
    const float* be = (const float*)d_in[8];
    const float* Wo = (const float*)d_in[9];
    const float* bo = (const float*)d_in[10];

    void *p_xb, *p_q, *p_k, *p_v, *p_vt, *p_attn, *p_h, *p_S, *p_P;
    void *p_Wq, *p_Wk, *p_Wv, *p_We, *p_Wo;
    cudaGetSymbolAddress(&p_xb, g_xb);
    cudaGetSymbolAddress(&p_q, g_q);
    cudaGetSymbolAddress(&p_k, g_k);
    cudaGetSymbolAddress(&p_v, g_v);
    cudaGetSymbolAddress(&p_vt, g_vt);
    cudaGetSymbolAddress(&p_attn, g_attn);
    cudaGetSymbolAddress(&p_h, g_h);
    cudaGetSymbolAddress(&p_S, g_S);
    cudaGetSymbolAddress(&p_P, g_P);
    cudaGetSymbolAddress(&p_Wq, g_Wq);
    cudaGetSymbolAddress(&p_Wk, g_Wk);
    cudaGetSymbolAddress(&p_Wv, g_Wv);
    cudaGetSymbolAddress(&p_We, g_We);
    cudaGetSymbolAddress(&p_Wo, g_Wo);

    cudaFuncSetAttribute(tc_gemm<0>, cudaFuncAttributeMaxDynamicSharedMemorySize, SMEM_BYTES);
    cudaFuncSetAttribute(tc_gemm<1>, cudaFuncAttributeMaxDynamicSharedMemorySize, SMEM_BYTES);
    cudaFuncSetAttribute(tc_gemm<2>, cudaFuncAttributeMaxDynamicSharedMemorySize, SMEM_BYTES);
    cudaFuncSetAttribute(tc_gemm<3>, cudaFuncAttributeMaxDynamicSharedMemorySize, SMEM_BYTES);
    cudaFuncSetAttribute(tc_gemm<4>, cudaFuncAttributeMaxDynamicSharedMemorySize, SMEM_BYTES);

    const float qscale = 1.0f / sqrtf((float)DREAL);
    dim3 blk(256);

    // launches 1-5: the pads GEMM-q depends on, plus We
    pad_cast(x,  p_xb, MROWS, DREAL, MROWS, DP);
    pad_cast(Wq, p_Wq, DREAL, DREAL, DP, DP);
    pad_cast(Wk, p_Wk, DREAL, DREAL, DP, DP);
    pad_cast(Wv, p_Wv, DREAL, DREAL, DP, DP);
    pad_cast(We, p_We, HREAL, DREAL, HP, DP);

    // launch 6: GEMM-q  <-- ncu -s 5 -c 1 captures THIS
    {
        dim3 grid(DP / 128, MROWS / 256, 1);  // (9,64)
        tc_gemm<1><<<grid, blk, SMEM_BYTES>>>(
            (const __nv_bfloat16*)p_xb, (const __nv_bfloat16*)p_Wq, p_q,
            DP, DP, DP, DP, DP, bq, DREAL, qscale, nullptr, 0, 0, 0);
    }

    // launch 7: remaining pad
    pad_cast(Wo, p_Wo, DREAL, HREAL, DP, HP);

    // k, v projections
    {
        dim3 grid(DP / 128, MROWS / 256, 1);  // (9,64)
        tc_gemm<1><<<grid, blk, SMEM_BYTES>>>(
            (const __nv_bfloat16*)p_xb, (const __nv_bfloat16*)p_Wk, p_k,
            DP, DP, DP, DP, DP, bk, DREAL, 1.0f, nullptr, 0, 0, 0);
        tc_gemm<1><<<grid, blk, SMEM_BYTES>>>(
            (const __nv_bfloat16*)p_xb, (const __nv_bfloat16*)p_Wv, p_v,
            DP, DP, DP, DP, DP, bv, DREAL, 1.0f, nullptr, 0, 0, 0);
    }

    // scores: per batch, S = q @ k^T (scale folded into q), bf16 out
    {
        dim3 grid(NPOS / 128, NPOS / 256, NBATCH);  // (16,8,8)
        tc_gemm<4><<<grid, blk, SMEM_BYTES>>>(
            (const __nv_bfloat16*)p_q, (const __nv_bfloat16*)p_k, p_S,
            DP, DP, DP, NPOS, NPOS, nullptr, 0, 1.0f, nullptr,
            (size_t)NPOS * DP, (size_t)NPOS * DP, (size_t)NPOS * NPOS);
    }

    // softmax rows (bf16 -> bf16)
    softmax_kernel<<<NBATCH * NPOS, 256>>>((const __nv_bfloat16*)p_S,
                                           (__nv_bfloat16*)p_P);

    // transpose V per batch: v[n,d] -> vt[d,n]
    {
        dim3 grid(NPOS / 32, DP / 32, NBATCH);  // (64,36,8)
        transpose_kernel<<<grid, blk>>>((const __nv_bfloat16*)p_v,
                                        (__nv_bfloat16*)p_vt);
    }

    // attn = P @ Vt^T
    {
        dim3 grid(DP / 128, NPOS / 256, NBATCH);  // (9,8,8)
        tc_gemm<4><<<grid, blk, SMEM_BYTES>>>(
            (const __nv_bfloat16*)p_P, (const __nv_bfloat16*)p_vt, p_attn,
            NPOS, NPOS, NPOS, DP, DP, nullptr, 0, 1.0f, nullptr,
            (size_t)NPOS * NPOS, (size_t)DP * NPOS, (size_t)NPOS * DP);
    }

    // h = gelu(attn @ We^T + be)
    {
        dim3 grid(HP / 128, MROWS / 256, 1);  // (33,64)
        tc_gemm<2><<<grid, blk, SMEM_BYTES>>>(
            (const __nv_bfloat16*)p_attn, (const __nv_bfloat16*)p_We, p_h,
            DP, DP, DP, HP, HP, be, HREAL, 1.0f, nullptr, 0, 0, 0);
    }

    // out = h @ Wo^T + bo + x  (fp32, width 1028 guarded)
    {
        dim3 grid((DREAL + 127) / 128, MROWS / 256, 1);  // (9,64)
        tc_gemm<3><<<grid, blk, SMEM_BYTES>>>(
            (const __nv_bfloat16*)p_h, (const __nv_bfloat16*)p_Wo, d_out,
            HP, HP, HP, DREAL, DREAL, bo, DREAL, 1.0f, x, 0, 0, 0);
    }
}